// round 10
// baseline (speedup 1.0000x reference)
#include <cuda_runtime.h>
#include <math.h>

// Shapes (compile-time constants from the reference)
#define T_DIM   512
#define B_DIM   32
#define TS_FD   76
#define N_WF    200
#define WF_LEN  1000
#define TEXT_D  200
#define WF_D    100
#define HID     256
#define FC_H    256
#define NCLS    2
#define ROWS    (T_DIM * B_DIM)          // 16384
#define FEAT_D  (TEXT_D + HID + WF_D)    // 556
#define C1_ELEMS (B_DIM * N_WF * WF_D)   // 640000

// Scratch (no cudaMalloc allowed): __device__ globals
__device__ float g_C1[C1_ELEMS];               // wf_out, (6400,100)
__device__ float g_P[3 * C1_ELEMS];            // split-K partials for stage 2
__device__ float g_feat[ROWS * FEAT_D];        // concatenated features (16384,556)
__device__ float g_H[ROWS * FC_H];             // relu hidden (16384,256)

enum { EPI_BIAS = 0, EPI_TANH = 1, EPI_SCALE = 2, EPI_RELU = 3 };

// ---------------------------------------------------------------------------
// 128x128x8 register-tiled fp32 GEMM, 256 threads, 8x8 per thread.
// Double-buffered smem with register-staged global prefetch: LDG for tile t+1
// is issued before the FFMA block for tile t (~2048 issue cycles) so DRAM/L2
// latency is hidden; one __syncthreads per k-tile.
// Batched via blockIdx.z strides (also used for split-K with partial outputs).
// M must be a multiple of 128 (all call sites: 6400, 16384, 512). N, K guarded.
// ---------------------------------------------------------------------------
template <int EPI>
__global__ __launch_bounds__(256, 2) void sgemm128(
    const float* __restrict__ A, int lda, long aStride,
    const float* __restrict__ B, int ldb, long bStride,
    float*       __restrict__ C, int ldc, long cStride,
    int N, int K,
    const float* __restrict__ bias, float scale)
{
    A += (long)blockIdx.z * aStride;
    B += (long)blockIdx.z * bStride;
    C += (long)blockIdx.z * cStride;

    const int row0 = blockIdx.y * 128;
    const int col0 = blockIdx.x * 128;
    const int tid  = threadIdx.x;
    const int tr   = tid >> 4;       // 0..15 (row group)
    const int tc   = tid & 15;       // 0..15 (col group)

    __shared__ float As[2][8][132];  // [buf][k][m], padded rows
    __shared__ float Bs[2][8][132];  // [buf][k][n]

    float acc[8][8];
#pragma unroll
    for (int i = 0; i < 8; i++)
#pragma unroll
        for (int j = 0; j < 8; j++) acc[i][j] = 0.f;

    const int ar = tid >> 1;           // 0..127 : A tile row
    const int ah = (tid & 1) * 4;      // 0 or 4 : A tile k-half
    const int bk = tid >> 5;           // 0..7   : B tile k-row
    const int bc = (tid & 31) * 4;     // 0..124 : B tile col

    const float* aBase = A + (long)(row0 + ar) * lda;

    // guarded global fetches into registers
    auto loadA = [&](int k0) -> float4 {
        const int kb = k0 + ah;
        const float* ap = aBase + kb;
        float4 av;
        if (kb + 3 < K) {
            av = *(const float4*)ap;
        } else {
            av.x = (kb + 0 < K) ? ap[0] : 0.f;
            av.y = (kb + 1 < K) ? ap[1] : 0.f;
            av.z = (kb + 2 < K) ? ap[2] : 0.f;
            av.w = (kb + 3 < K) ? ap[3] : 0.f;
        }
        return av;
    };
    auto loadB = [&](int k0) -> float4 {
        const int kb  = k0 + bk;
        const int col = col0 + bc;
        float4 bv = make_float4(0.f, 0.f, 0.f, 0.f);
        if (kb < K) {
            const float* bp = B + (long)kb * ldb + col;
            if (col + 3 < N) {
                bv = *(const float4*)bp;
            } else {
                if (col + 0 < N) bv.x = bp[0];
                if (col + 1 < N) bv.y = bp[1];
                if (col + 2 < N) bv.z = bp[2];
                if (col + 3 < N) bv.w = bp[3];
            }
        }
        return bv;
    };

    const int nt = (K + 7) / 8;

    // preload tile 0 into buffer 0
    float4 pa = loadA(0);
    float4 pb = loadB(0);
    As[0][ah + 0][ar] = pa.x;
    As[0][ah + 1][ar] = pa.y;
    As[0][ah + 2][ar] = pa.z;
    As[0][ah + 3][ar] = pa.w;
    *(float4*)&Bs[0][bk][bc] = pb;
    __syncthreads();

    for (int t = 0; t < nt; t++) {
        const int p = t & 1;
        const bool more = (t + 1 < nt);
        if (more) {                       // prefetch next tile (hidden by FFMAs)
            pa = loadA((t + 1) * 8);
            pb = loadB((t + 1) * 8);
        }

#pragma unroll
        for (int kk = 0; kk < 8; kk++) {
            float4 a0 = *(const float4*)&As[p][kk][tr * 8];
            float4 a1 = *(const float4*)&As[p][kk][tr * 8 + 4];
            float4 b0 = *(const float4*)&Bs[p][kk][tc * 8];
            float4 b1 = *(const float4*)&Bs[p][kk][tc * 8 + 4];
            float a[8] = {a0.x, a0.y, a0.z, a0.w, a1.x, a1.y, a1.z, a1.w};
            float b[8] = {b0.x, b0.y, b0.z, b0.w, b1.x, b1.y, b1.z, b1.w};
#pragma unroll
            for (int i = 0; i < 8; i++)
#pragma unroll
                for (int j = 0; j < 8; j++)
                    acc[i][j] = fmaf(a[i], b[j], acc[i][j]);
        }

        if (more) {                       // stage into the other buffer
            const int q = p ^ 1;
            As[q][ah + 0][ar] = pa.x;
            As[q][ah + 1][ar] = pa.y;
            As[q][ah + 2][ar] = pa.z;
            As[q][ah + 3][ar] = pa.w;
            *(float4*)&Bs[q][bk][bc] = pb;
        }
        __syncthreads();
    }

    // --- epilogue ---
#pragma unroll
    for (int i = 0; i < 8; i++) {
        const int r = row0 + tr * 8 + i;
#pragma unroll
        for (int j = 0; j < 8; j++) {
            const int col = col0 + tc * 8 + j;
            if (col < N) {
                float v = acc[i][j];
                if (EPI == EPI_BIAS)       v += bias[col];
                else if (EPI == EPI_TANH)  v = tanhf(v + bias[col]);
                else if (EPI == EPI_SCALE) v *= scale;
                else { v += bias[col]; v = v > 0.f ? v : 0.f; }
                C[(long)r * ldc + col] = v;
            }
        }
    }
}

// ---------------------------------------------------------------------------
// Reduce the 3 split-K partials of stage 2 and add bias: C1 = P0+P1+P2 + b_wf
// ---------------------------------------------------------------------------
__global__ __launch_bounds__(256) void reduce3_bias_kernel(const float* __restrict__ b_wf)
{
    const int idx = blockIdx.x * 256 + threadIdx.x;
    if (idx >= C1_ELEMS) return;
    const int c = idx % WF_D;
    g_C1[idx] = g_P[idx] + g_P[idx + C1_ELEMS] + g_P[idx + 2 * C1_ELEMS] + b_wf[c];
}

// ---------------------------------------------------------------------------
// Copy texts (16384 x 200, contiguous) into feat[:, 0:200] (ldc = 556)
// ---------------------------------------------------------------------------
__global__ __launch_bounds__(256) void pack_texts_kernel(const float* __restrict__ texts)
{
    const int idx = blockIdx.x * blockDim.x + threadIdx.x; // over ROWS * 50 float4s
    if (idx >= ROWS * (TEXT_D / 4)) return;
    const int r = idx / (TEXT_D / 4);
    const int c = idx % (TEXT_D / 4);
    float4 v = *(const float4*)(texts + (long)r * TEXT_D + c * 4);
    *(float4*)(g_feat + (long)r * FEAT_D + c * 4) = v;
}

// ---------------------------------------------------------------------------
// Head: out[r, c] = sum_j H[r, j] * W2[j, c] + b2[c].  One warp per row.
// ---------------------------------------------------------------------------
__global__ __launch_bounds__(256) void head_kernel(
    const float* __restrict__ H, const float* __restrict__ W2,
    const float* __restrict__ b2, float* __restrict__ out)
{
    __shared__ float w2s[FC_H * NCLS];
    const int tid = threadIdx.x;
    for (int i = tid; i < FC_H * NCLS; i += 256) w2s[i] = W2[i];
    __syncthreads();

    const int warp = tid >> 5;
    const int lane = tid & 31;
    const int r = blockIdx.x * 8 + warp;

    const float* h = H + (long)r * FC_H + lane * 8;
    float4 v0 = *(const float4*)(h);
    float4 v1 = *(const float4*)(h + 4);
    float hv[8] = {v0.x, v0.y, v0.z, v0.w, v1.x, v1.y, v1.z, v1.w};

    float s0 = 0.f, s1 = 0.f;
#pragma unroll
    for (int i = 0; i < 8; i++) {
        const int j = lane * 8 + i;
        s0 = fmaf(hv[i], w2s[j * 2 + 0], s0);
        s1 = fmaf(hv[i], w2s[j * 2 + 1], s1);
    }
#pragma unroll
    for (int m = 16; m > 0; m >>= 1) {
        s0 += __shfl_xor_sync(0xFFFFFFFFu, s0, m);
        s1 += __shfl_xor_sync(0xFFFFFFFFu, s1, m);
    }
    if (lane == 0) {
        out[(long)r * NCLS + 0] = s0 + b2[0];
        out[(long)r * NCLS + 1] = s1 + b2[1];
    }
}

// ---------------------------------------------------------------------------
extern "C" void kernel_launch(void* const* d_in, const int* in_sizes, int n_in,
                              void* d_out, int out_size)
{
    const float* texts = (const float*)d_in[0];   // (512,32,200)
    const float* ts    = (const float*)d_in[1];   // (512,32,76)
    const float* wave  = (const float*)d_in[2];   // (32,200,1000)
    const float* wwm   = (const float*)d_in[3];   // (32,512,200)
    const float* W_wf  = (const float*)d_in[4];   // (1000,100)
    const float* b_wf  = (const float*)d_in[5];
    const float* W_ts  = (const float*)d_in[6];   // (76,256)
    const float* b_ts  = (const float*)d_in[7];
    const float* W1    = (const float*)d_in[8];   // (556,256)
    const float* b1    = (const float*)d_in[9];
    const float* W2    = (const float*)d_in[10];  // (256,2)
    const float* b2    = (const float*)d_in[11];
    float* out = (float*)d_out;

    float *C1, *P, *feat, *H;
    cudaGetSymbolAddress((void**)&C1,   g_C1);
    cudaGetSymbolAddress((void**)&P,    g_P);
    cudaGetSymbolAddress((void**)&feat, g_feat);
    cudaGetSymbolAddress((void**)&H,    g_H);

    // 1) feat[:, 0:200] = texts (t-major rows, matching output rows)
    pack_texts_kernel<<<(ROWS * (TEXT_D / 4) + 255) / 256, 256>>>(texts);

    // 2) C1 = waveform @ W_wf + b_wf : (6400 x 100 x 1000), split-K=3 (336/336/328)
    //    z indexes the k-chunk: A shifts by 336 in k, B by 336 rows, C to partial z.
    sgemm128<EPI_SCALE><<<dim3(1, 50, 2), 256>>>(
        wave, WF_LEN, 336,
        W_wf, WF_D, (long)336 * WF_D,
        P, WF_D, (long)C1_ELEMS,
        WF_D, 336, nullptr, 1.f);
    sgemm128<EPI_SCALE><<<dim3(1, 50, 1), 256>>>(
        wave + 672, WF_LEN, 0,
        W_wf + (long)672 * WF_D, WF_D, 0,
        P + (long)2 * C1_ELEMS, WF_D, 0,
        WF_D, 328, nullptr, 1.f);
    reduce3_bias_kernel<<<(C1_ELEMS + 255) / 256, 256>>>(b_wf);

    // 3) feat[:, 200:456] = tanh(ts @ W_ts + b_ts) : (16384 x 256 x 76)
    sgemm128<EPI_TANH><<<dim3(2, 128, 1), 256>>>(
        ts, TS_FD, 0, W_ts, HID, 0, feat + TEXT_D, FEAT_D, 0,
        HID, TS_FD, b_ts, 1.f);

    // 4) feat[:, 456:556] = bmm(wwm, C1) / 200 : 32 x (512 x 100 x 200)
    sgemm128<EPI_SCALE><<<dim3(1, 4, 32), 256>>>(
        wwm, N_WF, (long)T_DIM * N_WF,
        C1, WF_D, (long)N_WF * WF_D,
        feat + TEXT_D + HID, FEAT_D, (long)T_DIM * FEAT_D,
        WF_D, N_WF, nullptr, 1.f / (float)N_WF);

    // 5) H = relu(feat @ W1 + b1) : (16384 x 256 x 556)
    sgemm128<EPI_RELU><<<dim3(2, 128, 1), 256>>>(
        feat, FEAT_D, 0, W1, FC_H, 0, H, FC_H, 0,
        FC_H, FEAT_D, b1, 1.f);

    // 6) out = H @ W2 + b2 : (16384 x 2 x 256)
    head_kernel<<<ROWS / 8, 256>>>(H, W2, b2, out);
}

// round 12
// speedup vs baseline: 1.4317x; 1.4317x over previous
#include <cuda_runtime.h>
#include <cuda_bf16.h>
#include <math.h>
#include <stdint.h>

// ---------------- shapes ----------------
#define T_DIM   512
#define B_DIM   32
#define TS_FD   76
#define N_WF    200
#define WF_LEN  1000
#define TEXT_D  200
#define WF_D    100
#define HID     256
#define FC_H    256
#define NCLS    2
#define ROWS    (T_DIM * B_DIM)          // 16384
#define C1_ELEMS (B_DIM * N_WF * WF_D)   // 640000

// ---------------- scratch (__device__ globals; no cudaMalloc) ----------------
__device__ float g_C1[C1_ELEMS];               // wf_out (6400,100)
__device__ float g_P[2 * C1_ELEMS];            // stage-2 split-K partials
__device__ float g_TS[ROWS * HID];             // tanh(ts proj) (16384,256)
__device__ float g_SP[ROWS * WF_D];            // spread (16384,100), rows b*512+t
__device__ float g_H[ROWS * FC_H];             // relu hidden (16384,256)
__device__ __align__(16) __nv_bfloat16 g_Baug[1 << 22];  // augmented B (hi,hi,lo thirds)

enum { EPI_TANH = 0, EPI_SCALE = 1, EPI_RELU = 2 };

// ---------------- PTX helpers (sm_80-level: ldmatrix + HMMA bf16) ----------------
__device__ __forceinline__ uint32_t smem_u32(const void* p) {
    uint32_t a;
    asm("{ .reg .u64 t; cvta.to.shared.u64 t, %1; cvt.u32.u64 %0, t; }" : "=r"(a) : "l"(p));
    return a;
}

#define LDSM4(r0, r1, r2, r3, a) \
    asm volatile("ldmatrix.sync.aligned.m8n8.x4.shared.b16 {%0,%1,%2,%3}, [%4];" \
        : "=r"(r0), "=r"(r1), "=r"(r2), "=r"(r3) : "r"(a))

#define MMA_BF16(d, a, b) \
    asm volatile("mma.sync.aligned.m16n8k16.row.col.f32.bf16.bf16.f32 " \
        "{%0,%1,%2,%3}, {%4,%5,%6,%7}, {%8,%9}, {%0,%1,%2,%3};" \
        : "+f"((d)[0]), "+f"((d)[1]), "+f"((d)[2]), "+f"((d)[3]) \
        : "r"((a)[0]), "r"((a)[1]), "r"((a)[2]), "r"((a)[3]), \
          "r"((b)[0]), "r"((b)[1]))

// ---------------------------------------------------------------------------
// B prep: from fp32 src [K, N] (row stride ld, batch stride sStr) build the
// K-augmented bf16 array g_Baug [z][NT][3*KP3]: third0 = hi, third1 = hi,
// third2 = lo  (pairs with A thirds hi, lo, hi). Zero padded (n>=N, k>=K).
// ---------------------------------------------------------------------------
__global__ __launch_bounds__(256) void prep_baug(
    const float* __restrict__ src, int ld, long sStr,
    int N, int K, int KP3, int NT)
{
    const int  z   = blockIdx.y;
    const long per = (long)NT * 3 * KP3;
    const int  idx = blockIdx.x * 256 + threadIdx.x;
    if (idx >= per) return;
    const int n     = idx / (3 * KP3);
    const int ak    = idx % (3 * KP3);
    const int third = ak / KP3;
    const int k     = ak - third * KP3;
    float v = 0.f;
    if (n < N && k < K) v = src[(long)z * sStr + (long)k * ld + n];
    __nv_bfloat16 h = __float2bfloat16_rn(v);
    g_Baug[(long)z * per + idx] =
        (third == 2) ? __float2bfloat16_rn(v - __bfloat162float(h)) : h;
}

// ---------------------------------------------------------------------------
// bf16 HMMA GEMM over the augmented K dimension.
// CTA: 256 threads (8 warps), tile 128 x NT.  Warp tile WM x WN.
// A: fp32 in global, converted per 32-k chunk to hi/lo bf16 (by third) into
//    smem [128][40] bf16 (pad-40 rows -> conflict-free ldmatrix).
// B: pre-augmented bf16 [NT][3*KP3] -> smem [NT][40].
// Double buffered, register-prefetch, one __syncthreads per chunk.
// z (blockIdx.z) provides batch offsets AND/OR a split-K chunk offset.
// GATHER: A columns come from texts / g_TS / g_SP (bounds 200/456, all /4).
// ---------------------------------------------------------------------------
template<int NT, int WM, int WN, int EPI, bool GATHER>
__global__ __launch_bounds__(256, 1) void hgemm(
    const float* __restrict__ A, int lda, long aStr,
    const float* __restrict__ A2, const float* __restrict__ A3,
    const __nv_bfloat16* __restrict__ Baug, long bStr, int KP3,
    float* __restrict__ C, int ldc, long cStr,
    int N, int K, int NC, int zChunkOff,
    const float* __restrict__ bias, float scale)
{
    extern __shared__ char smem[];
    constexpr int MI   = WM / 16;
    constexpr int NI   = WN / 8;
    constexpr int NWC  = NT / WN;
    constexpr int ABUF = 128 * 80;             // bytes per A buffer
    constexpr int BBUF = NT * 80;

    const int tid  = threadIdx.x;
    const int lane = tid & 31;
    const int wid  = tid >> 5;
    const int wr   = wid / NWC;
    const int wc   = wid % NWC;

    A    += (long)blockIdx.z * aStr;
    Baug += (long)blockIdx.z * bStr;
    C    += (long)blockIdx.z * cStr;
    const int row0g = blockIdx.y * 128;

    const uint32_t sb = smem_u32(smem);
    // ldmatrix lane addresses (byte offsets inside buffers)
    const uint32_t aAddr = sb +
        (((wr * WM + (lane & 15)) * 40 + ((lane >> 4) * 8)) << 1);
    const uint32_t bAddr = sb + 2 * ABUF +
        (((wc * WN + (lane & 7) + ((lane >> 4) * 8)) * 40 + (((lane >> 3) & 1) * 8)) << 1);

    float acc[MI][NI][4];
#pragma unroll
    for (int mi = 0; mi < MI; mi++)
#pragma unroll
        for (int ni = 0; ni < NI; ni++)
#pragma unroll
            for (int q = 0; q < 4; q++) acc[mi][ni][q] = 0.f;

    const int  arow = tid >> 1;
    const int  ch   = (tid & 1) * 16;
    const long rA   = row0g + arow;

    float4 va[4];
    uint4  vb[4];
    bool   aLo = false;

    auto loadA = [&](int g) {
        const int bk    = g * 32;
        const int third = bk / KP3;
        aLo = (third == 1);
        const int s0 = bk - third * KP3 + ch;
#pragma unroll
        for (int q = 0; q < 4; q++) {
            const int sc = s0 + q * 4;
            float4 f = make_float4(0.f, 0.f, 0.f, 0.f);
            if (sc < K) {
                const float* p;
                if (!GATHER)                    p = A  + rA * (long)lda    + sc;
                else if (sc < TEXT_D)           p = A  + rA * (long)TEXT_D + sc;
                else if (sc < TEXT_D + HID)     p = A2 + rA * (long)HID    + (sc - TEXT_D);
                else                            p = A3 + rA * (long)WF_D   + (sc - TEXT_D - HID);
                f = *(const float4*)p;
            }
            va[q] = f;
        }
    };
    auto storeA = [&](int buf) {
        __nv_bfloat16 hv[16];
        const float* vf = (const float*)va;
#pragma unroll
        for (int i = 0; i < 16; i++) {
            float v = vf[i];
            __nv_bfloat16 h = __float2bfloat16_rn(v);
            hv[i] = aLo ? __float2bfloat16_rn(v - __bfloat162float(h)) : h;
        }
        char* dst = smem + buf * ABUF + ((arow * 40 + ch) << 1);
        *(uint4*)dst        = *(const uint4*)&hv[0];
        *(uint4*)(dst + 16) = *(const uint4*)&hv[8];
    };
    auto loadB = [&](int g) {
        if (tid < NT) {
            const uint4* p = (const uint4*)(Baug + (long)tid * (3 * KP3) + g * 32);
            vb[0] = p[0]; vb[1] = p[1]; vb[2] = p[2]; vb[3] = p[3];
        }
    };
    auto storeB = [&](int buf) {
        if (tid < NT) {
            char* dst = smem + 2 * ABUF + buf * BBUF + tid * 80;
            *(uint4*)dst        = vb[0];
            *(uint4*)(dst + 16) = vb[1];
            *(uint4*)(dst + 32) = vb[2];
            *(uint4*)(dst + 48) = vb[3];
        }
    };

    const int g0 = blockIdx.z * zChunkOff;

    loadA(g0); loadB(g0);
    storeA(0); storeB(0);
    __syncthreads();

    for (int c = 0; c < NC; c++) {
        const int  p    = c & 1;
        const bool more = (c + 1 < NC);
        if (more) { loadA(g0 + c + 1); loadB(g0 + c + 1); }

#pragma unroll
        for (int kk = 0; kk < 2; kk++) {
            uint32_t af[MI][4];
#pragma unroll
            for (int mi = 0; mi < MI; mi++)
                LDSM4(af[mi][0], af[mi][1], af[mi][2], af[mi][3],
                      aAddr + p * ABUF + mi * (16 * 80) + kk * 32);
            uint32_t bfr[NI][2];
#pragma unroll
            for (int nb = 0; nb < NI / 2; nb++)
                LDSM4(bfr[2 * nb][0], bfr[2 * nb][1], bfr[2 * nb + 1][0], bfr[2 * nb + 1][1],
                      bAddr + p * BBUF + nb * (16 * 80) + kk * 32);
#pragma unroll
            for (int mi = 0; mi < MI; mi++)
#pragma unroll
                for (int ni = 0; ni < NI; ni++)
                    MMA_BF16(acc[mi][ni], af[mi], bfr[ni]);
        }

        if (more) { storeA(p ^ 1); storeB(p ^ 1); }
        __syncthreads();
    }

    // ---- epilogue: fragment (r = l/4 [+8], c = (l%4)*2) ----
    const int rw = row0g + wr * WM + (lane >> 2);
    const int cw = wc * WN + (lane & 3) * 2;
#pragma unroll
    for (int mi = 0; mi < MI; mi++) {
#pragma unroll
        for (int ni = 0; ni < NI; ni++) {
            const int col = cw + ni * 8;
            if (col < N) {
                float v0 = acc[mi][ni][0], v1 = acc[mi][ni][1];
                float v2 = acc[mi][ni][2], v3 = acc[mi][ni][3];
                if (EPI == EPI_TANH) {
                    const float b0 = bias[col], b1 = bias[col + 1];
                    v0 = tanhf(v0 + b0); v1 = tanhf(v1 + b1);
                    v2 = tanhf(v2 + b0); v3 = tanhf(v3 + b1);
                } else if (EPI == EPI_SCALE) {
                    v0 *= scale; v1 *= scale; v2 *= scale; v3 *= scale;
                } else {  // RELU
                    const float b0 = bias[col], b1 = bias[col + 1];
                    v0 += b0; v1 += b1; v2 += b0; v3 += b1;
                    v0 = v0 > 0.f ? v0 : 0.f; v1 = v1 > 0.f ? v1 : 0.f;
                    v2 = v2 > 0.f ? v2 : 0.f; v3 = v3 > 0.f ? v3 : 0.f;
                }
                const int r1 = rw + mi * 16;
                *(float2*)(C + (long)r1 * ldc + col)       = make_float2(v0, v1);
                *(float2*)(C + (long)(r1 + 8) * ldc + col) = make_float2(v2, v3);
            }
        }
    }
}

// ---------------------------------------------------------------------------
// stage-2 split-K reduce + bias: C1 = P0 + P1 + b_wf
// ---------------------------------------------------------------------------
__global__ __launch_bounds__(256) void reduce2_bias(const float* __restrict__ b_wf)
{
    const int idx = blockIdx.x * 256 + threadIdx.x;
    if (idx >= C1_ELEMS) return;
    g_C1[idx] = g_P[idx] + g_P[idx + C1_ELEMS] + b_wf[idx % WF_D];
}

// ---------------------------------------------------------------------------
// Head: out[r, c] = sum_j H[r, j] * W2[j, c] + b2[c].  One warp per row.
// ---------------------------------------------------------------------------
__global__ __launch_bounds__(256) void head_kernel(
    const float* __restrict__ H, const float* __restrict__ W2,
    const float* __restrict__ b2, float* __restrict__ out)
{
    __shared__ float w2s[FC_H * NCLS];
    const int tid = threadIdx.x;
    for (int i = tid; i < FC_H * NCLS; i += 256) w2s[i] = W2[i];
    __syncthreads();

    const int warp = tid >> 5;
    const int lane = tid & 31;
    const int r = blockIdx.x * 8 + warp;

    const float* h = H + (long)r * FC_H + lane * 8;
    float4 v0 = *(const float4*)(h);
    float4 v1 = *(const float4*)(h + 4);
    float hv[8] = {v0.x, v0.y, v0.z, v0.w, v1.x, v1.y, v1.z, v1.w};

    float s0 = 0.f, s1 = 0.f;
#pragma unroll
    for (int i = 0; i < 8; i++) {
        const int j = lane * 8 + i;
        s0 = fmaf(hv[i], w2s[j * 2 + 0], s0);
        s1 = fmaf(hv[i], w2s[j * 2 + 1], s1);
    }
#pragma unroll
    for (int m = 16; m > 0; m >>= 1) {
        s0 += __shfl_xor_sync(0xFFFFFFFFu, s0, m);
        s1 += __shfl_xor_sync(0xFFFFFFFFu, s1, m);
    }
    if (lane == 0) {
        out[(long)r * NCLS + 0] = s0 + b2[0];
        out[(long)r * NCLS + 1] = s1 + b2[1];
    }
}

// ---------------------------------------------------------------------------
extern "C" void kernel_launch(void* const* d_in, const int* in_sizes, int n_in,
                              void* d_out, int out_size)
{
    const float* texts = (const float*)d_in[0];   // (512,32,200)
    const float* ts    = (const float*)d_in[1];   // (512,32,76)
    const float* wave  = (const float*)d_in[2];   // (32,200,1000)
    const float* wwm   = (const float*)d_in[3];   // (32,512,200)
    const float* W_wf  = (const float*)d_in[4];   // (1000,100)
    const float* b_wf  = (const float*)d_in[5];
    const float* W_ts  = (const float*)d_in[6];   // (76,256)
    const float* b_ts  = (const float*)d_in[7];
    const float* W1    = (const float*)d_in[8];   // (556,256)
    const float* b1    = (const float*)d_in[9];
    const float* W2    = (const float*)d_in[10];  // (256,2)
    const float* b2    = (const float*)d_in[11];
    float* out = (float*)d_out;

    float *C1, *P, *TS, *SP, *H;
    __nv_bfloat16* Baug;
    cudaGetSymbolAddress((void**)&C1,   g_C1);
    cudaGetSymbolAddress((void**)&P,    g_P);
    cudaGetSymbolAddress((void**)&TS,   g_TS);
    cudaGetSymbolAddress((void**)&SP,   g_SP);
    cudaGetSymbolAddress((void**)&H,    g_H);
    cudaGetSymbolAddress((void**)&Baug, g_Baug);

    const int SMEM_N128 = 4 * 128 * 80;               // 40960
    const int SMEM_N256 = 2 * 128 * 80 + 2 * 256 * 80; // 61440
    cudaFuncSetAttribute(hgemm<128, 32, 64, EPI_SCALE, false>,
                         cudaFuncAttributeMaxDynamicSharedMemorySize, SMEM_N128);
    cudaFuncSetAttribute(hgemm<256, 64, 64, EPI_TANH, false>,
                         cudaFuncAttributeMaxDynamicSharedMemorySize, SMEM_N256);
    cudaFuncSetAttribute(hgemm<256, 64, 64, EPI_RELU, true>,
                         cudaFuncAttributeMaxDynamicSharedMemorySize, SMEM_N256);

    // ---- stage 2: C1 = waveform @ W_wf + b_wf (6400 x 100 x 1000), split-K=2
    // KP3 = 1024 -> K3 = 3072 -> 96 chunks; z handles 48 chunks each.
    prep_baug<<<dim3(1536, 1), 256>>>(W_wf, WF_D, 0, WF_D, WF_LEN, 1024, 128);
    hgemm<128, 32, 64, EPI_SCALE, false><<<dim3(1, 50, 2), 256, SMEM_N128>>>(
        wave, WF_LEN, 0, nullptr, nullptr,
        Baug, 0, 1024,
        P, WF_D, (long)C1_ELEMS,
        WF_D, WF_LEN, 48, 48, nullptr, 1.f);
    reduce2_bias<<<(C1_ELEMS + 255) / 256, 256>>>(b_wf);

    // ---- stage 3: g_TS = tanh(ts @ W_ts + b_ts) (16384 x 256 x 76)
    // KP3 = 96 -> 9 chunks.
    prep_baug<<<dim3(288, 1), 256>>>(W_ts, HID, 0, HID, TS_FD, 96, 256);
    hgemm<256, 64, 64, EPI_TANH, false><<<dim3(1, 128, 1), 256, SMEM_N256>>>(
        ts, TS_FD, 0, nullptr, nullptr,
        Baug, 0, 96,
        TS, HID, 0,
        HID, TS_FD, 9, 0, b_ts, 1.f);

    // ---- stage 4: g_SP = bmm(wwm, C1) / 200 (32 x [512 x 100 x 200])
    // KP3 = 224 -> 21 chunks; z = batch.
    prep_baug<<<dim3(336, 32), 256>>>(C1, WF_D, (long)N_WF * WF_D, WF_D, N_WF, 224, 128);
    hgemm<128, 32, 64, EPI_SCALE, false><<<dim3(1, 4, 32), 256, SMEM_N128>>>(
        wwm, N_WF, (long)T_DIM * N_WF, nullptr, nullptr,
        Baug, (long)128 * 672, 224,
        SP, WF_D, (long)T_DIM * WF_D,
        WF_D, N_WF, 21, 0, nullptr, 1.f / (float)N_WF);

    // ---- stage 5: g_H = relu([texts|g_TS|g_SP] @ W1 + b1) (16384 x 256 x 556)
    // KP3 = 576 -> 54 chunks; A gathered from the three sources.
    prep_baug<<<dim3(1728, 1), 256>>>(W1, FC_H, 0, FC_H, 556, 576, 256);
    hgemm<256, 64, 64, EPI_RELU, true><<<dim3(1, 128, 1), 256, SMEM_N256>>>(
        texts, 0, 0, TS, SP,
        Baug, 0, 576,
        H, FC_H, 0,
        FC_H, 556, 54, 0, b1, 1.f);

    // ---- head: out = H @ W2 + b2 (16384 x 2 x 256)
    head_kernel<<<ROWS / 8, 256>>>(H, W2, b2, out);
}

// round 13
// speedup vs baseline: 1.4357x; 1.0027x over previous
#include <cuda_runtime.h>
#include <cuda_bf16.h>
#include <math.h>
#include <stdint.h>

// ---------------- shapes ----------------
#define T_DIM   512
#define B_DIM   32
#define TS_FD   76
#define N_WF    200
#define WF_LEN  1000
#define TEXT_D  200
#define WF_D    100
#define HID     256
#define FC_H    256
#define NCLS    2
#define ROWS    (T_DIM * B_DIM)          // 16384
#define C1_ELEMS (B_DIM * N_WF * WF_D)   // 640000

// ---------------- scratch (__device__ globals; no cudaMalloc) ----------------
__device__ float g_C1[C1_ELEMS];               // wf_out (6400,100)
__device__ float g_P[2 * C1_ELEMS];            // stage-2 split-K partials
__device__ float g_TS[ROWS * HID];             // tanh(ts proj) (16384,256)
__device__ float g_SP[ROWS * WF_D];            // spread (16384,100), rows b*512+t
__device__ float g_H[ROWS * FC_H];             // relu hidden (16384,256)
__device__ __align__(16) __nv_bfloat16 g_Baug[1 << 22];  // augmented B (hi,hi,lo thirds)

enum { EPI_TANH = 0, EPI_SCALE = 1, EPI_RELU = 2 };

// ---------------- PTX helpers (sm_80-level: ldmatrix + HMMA bf16) ----------------
__device__ __forceinline__ uint32_t smem_u32(const void* p) {
    uint32_t a;
    asm("{ .reg .u64 t; cvta.to.shared.u64 t, %1; cvt.u32.u64 %0, t; }" : "=r"(a) : "l"(p));
    return a;
}

#define LDSM4(r0, r1, r2, r3, a) \
    asm volatile("ldmatrix.sync.aligned.m8n8.x4.shared.b16 {%0,%1,%2,%3}, [%4];" \
        : "=r"(r0), "=r"(r1), "=r"(r2), "=r"(r3) : "r"(a))

#define MMA_BF16(d, a, b) \
    asm volatile("mma.sync.aligned.m16n8k16.row.col.f32.bf16.bf16.f32 " \
        "{%0,%1,%2,%3}, {%4,%5,%6,%7}, {%8,%9}, {%0,%1,%2,%3};" \
        : "+f"((d)[0]), "+f"((d)[1]), "+f"((d)[2]), "+f"((d)[3]) \
        : "r"((a)[0]), "r"((a)[1]), "r"((a)[2]), "r"((a)[3]), \
          "r"((b)[0]), "r"((b)[1]))

// ---------------------------------------------------------------------------
// B prep: from fp32 src [K, N] (row stride ld, batch stride sStr) build the
// K-augmented bf16 array g_Baug [z][NT][3*KP3]: third0 = hi, third1 = hi,
// third2 = lo  (pairs with A thirds hi, lo, hi). Zero padded (n>=N, k>=K).
// ---------------------------------------------------------------------------
__global__ __launch_bounds__(256) void prep_baug(
    const float* __restrict__ src, int ld, long sStr,
    int N, int K, int KP3, int NT)
{
    const int  z   = blockIdx.y;
    const long per = (long)NT * 3 * KP3;
    const int  idx = blockIdx.x * 256 + threadIdx.x;
    if (idx >= per) return;
    const int n     = idx / (3 * KP3);
    const int ak    = idx % (3 * KP3);
    const int third = ak / KP3;
    const int k     = ak - third * KP3;
    float v = 0.f;
    if (n < N && k < K) v = src[(long)z * sStr + (long)k * ld + n];
    __nv_bfloat16 h = __float2bfloat16_rn(v);
    g_Baug[(long)z * per + idx] =
        (third == 2) ? __float2bfloat16_rn(v - __bfloat162float(h)) : h;
}

// ---------------------------------------------------------------------------
// bf16 HMMA GEMM over the augmented K dimension.
// CTA: 256 threads (8 warps), tile 128 x NT.  Warp tile WM x WN.
// A: fp32 in global, converted per 32-k chunk to hi/lo bf16 (by third) into
//    smem [128][40] bf16 (pad-40 rows -> conflict-free ldmatrix).
// B: pre-augmented bf16 [NT][3*KP3] -> smem [NT][40].
// Double buffered, register-prefetch, one __syncthreads per chunk.
// z (blockIdx.z) provides batch offsets AND/OR a split-K chunk offset.
// GATHER: A columns come from texts / g_TS / g_SP (bounds 200/456, all /4).
// ---------------------------------------------------------------------------
template<int NT, int WM, int WN, int EPI, bool GATHER>
__global__ __launch_bounds__(256, 1) void hgemm(
    const float* __restrict__ A, int lda, long aStr,
    const float* __restrict__ A2, const float* __restrict__ A3,
    const __nv_bfloat16* __restrict__ Baug, long bStr, int KP3,
    float* __restrict__ C, int ldc, long cStr,
    int N, int K, int NC, int zChunkOff,
    const float* __restrict__ bias, float scale)
{
    extern __shared__ char smem[];
    constexpr int MI   = WM / 16;
    constexpr int NI   = WN / 8;
    constexpr int NWC  = NT / WN;
    constexpr int ABUF = 128 * 80;             // bytes per A buffer
    constexpr int BBUF = NT * 80;

    const int tid  = threadIdx.x;
    const int lane = tid & 31;
    const int wid  = tid >> 5;
    const int wr   = wid / NWC;
    const int wc   = wid % NWC;

    A    += (long)blockIdx.z * aStr;
    Baug += (long)blockIdx.z * bStr;
    C    += (long)blockIdx.z * cStr;
    const int row0g = blockIdx.y * 128;

    const uint32_t sb = smem_u32(smem);
    // ldmatrix lane addresses (byte offsets inside buffers)
    const uint32_t aAddr = sb +
        (((wr * WM + (lane & 15)) * 40 + ((lane >> 4) * 8)) << 1);
    const uint32_t bAddr = sb + 2 * ABUF +
        (((wc * WN + (lane & 7) + ((lane >> 4) * 8)) * 40 + (((lane >> 3) & 1) * 8)) << 1);

    float acc[MI][NI][4];
#pragma unroll
    for (int mi = 0; mi < MI; mi++)
#pragma unroll
        for (int ni = 0; ni < NI; ni++)
#pragma unroll
            for (int q = 0; q < 4; q++) acc[mi][ni][q] = 0.f;

    const int  arow = tid >> 1;
    const int  ch   = (tid & 1) * 16;
    const long rA   = row0g + arow;

    float4 va[4];
    uint4  vb[4];
    bool   aLo = false;

    auto loadA = [&](int g) {
        const int bk    = g * 32;
        const int third = bk / KP3;
        aLo = (third == 1);
        const int s0 = bk - third * KP3 + ch;
#pragma unroll
        for (int q = 0; q < 4; q++) {
            const int sc = s0 + q * 4;
            float4 f = make_float4(0.f, 0.f, 0.f, 0.f);
            if (sc < K) {
                const float* p;
                if (!GATHER)                    p = A  + rA * (long)lda    + sc;
                else if (sc < TEXT_D)           p = A  + rA * (long)TEXT_D + sc;
                else if (sc < TEXT_D + HID)     p = A2 + rA * (long)HID    + (sc - TEXT_D);
                else                            p = A3 + rA * (long)WF_D   + (sc - TEXT_D - HID);
                f = *(const float4*)p;
            }
            va[q] = f;
        }
    };
    auto storeA = [&](int buf) {
        __nv_bfloat16 hv[16];
        const float* vf = (const float*)va;
#pragma unroll
        for (int i = 0; i < 16; i++) {
            float v = vf[i];
            __nv_bfloat16 h = __float2bfloat16_rn(v);
            hv[i] = aLo ? __float2bfloat16_rn(v - __bfloat162float(h)) : h;
        }
        char* dst = smem + buf * ABUF + ((arow * 40 + ch) << 1);
        *(uint4*)dst        = *(const uint4*)&hv[0];
        *(uint4*)(dst + 16) = *(const uint4*)&hv[8];
    };
    auto loadB = [&](int g) {
        if (tid < NT) {
            const uint4* p = (const uint4*)(Baug + (long)tid * (3 * KP3) + g * 32);
            vb[0] = p[0]; vb[1] = p[1]; vb[2] = p[2]; vb[3] = p[3];
        }
    };
    auto storeB = [&](int buf) {
        if (tid < NT) {
            char* dst = smem + 2 * ABUF + buf * BBUF + tid * 80;
            *(uint4*)dst        = vb[0];
            *(uint4*)(dst + 16) = vb[1];
            *(uint4*)(dst + 32) = vb[2];
            *(uint4*)(dst + 48) = vb[3];
        }
    };

    const int g0 = blockIdx.z * zChunkOff;

    loadA(g0); loadB(g0);
    storeA(0); storeB(0);
    __syncthreads();

    for (int c = 0; c < NC; c++) {
        const int  p    = c & 1;
        const bool more = (c + 1 < NC);
        if (more) { loadA(g0 + c + 1); loadB(g0 + c + 1); }

#pragma unroll
        for (int kk = 0; kk < 2; kk++) {
            uint32_t af[MI][4];
#pragma unroll
            for (int mi = 0; mi < MI; mi++)
                LDSM4(af[mi][0], af[mi][1], af[mi][2], af[mi][3],
                      aAddr + p * ABUF + mi * (16 * 80) + kk * 32);
            uint32_t bfr[NI][2];
#pragma unroll
            for (int nb = 0; nb < NI / 2; nb++)
                LDSM4(bfr[2 * nb][0], bfr[2 * nb][1], bfr[2 * nb + 1][0], bfr[2 * nb + 1][1],
                      bAddr + p * BBUF + nb * (16 * 80) + kk * 32);
#pragma unroll
            for (int mi = 0; mi < MI; mi++)
#pragma unroll
                for (int ni = 0; ni < NI; ni++)
                    MMA_BF16(acc[mi][ni], af[mi], bfr[ni]);
        }

        if (more) { storeA(p ^ 1); storeB(p ^ 1); }
        __syncthreads();
    }

    // ---- epilogue: fragment (r = l/4 [+8], c = (l%4)*2) ----
    const int rw = row0g + wr * WM + (lane >> 2);
    const int cw = wc * WN + (lane & 3) * 2;
#pragma unroll
    for (int mi = 0; mi < MI; mi++) {
#pragma unroll
        for (int ni = 0; ni < NI; ni++) {
            const int col = cw + ni * 8;
            if (col < N) {
                float v0 = acc[mi][ni][0], v1 = acc[mi][ni][1];
                float v2 = acc[mi][ni][2], v3 = acc[mi][ni][3];
                if (EPI == EPI_TANH) {
                    const float b0 = bias[col], b1 = bias[col + 1];
                    v0 = tanhf(v0 + b0); v1 = tanhf(v1 + b1);
                    v2 = tanhf(v2 + b0); v3 = tanhf(v3 + b1);
                } else if (EPI == EPI_SCALE) {
                    v0 *= scale; v1 *= scale; v2 *= scale; v3 *= scale;
                } else {  // RELU
                    const float b0 = bias[col], b1 = bias[col + 1];
                    v0 += b0; v1 += b1; v2 += b0; v3 += b1;
                    v0 = v0 > 0.f ? v0 : 0.f; v1 = v1 > 0.f ? v1 : 0.f;
                    v2 = v2 > 0.f ? v2 : 0.f; v3 = v3 > 0.f ? v3 : 0.f;
                }
                const int r1 = rw + mi * 16;
                *(float2*)(C + (long)r1 * ldc + col)       = make_float2(v0, v1);
                *(float2*)(C + (long)(r1 + 8) * ldc + col) = make_float2(v2, v3);
            }
        }
    }
}

// ---------------------------------------------------------------------------
// stage-2 split-K reduce + bias: C1 = P0 + P1 + b_wf
// ---------------------------------------------------------------------------
__global__ __launch_bounds__(256) void reduce2_bias(const float* __restrict__ b_wf)
{
    const int idx = blockIdx.x * 256 + threadIdx.x;
    if (idx >= C1_ELEMS) return;
    g_C1[idx] = g_P[idx] + g_P[idx + C1_ELEMS] + b_wf[idx % WF_D];
}

// ---------------------------------------------------------------------------
// Head: out[r, c] = sum_j H[r, j] * W2[j, c] + b2[c].  One warp per row.
// ---------------------------------------------------------------------------
__global__ __launch_bounds__(256) void head_kernel(
    const float* __restrict__ H, const float* __restrict__ W2,
    const float* __restrict__ b2, float* __restrict__ out)
{
    __shared__ float w2s[FC_H * NCLS];
    const int tid = threadIdx.x;
    for (int i = tid; i < FC_H * NCLS; i += 256) w2s[i] = W2[i];
    __syncthreads();

    const int warp = tid >> 5;
    const int lane = tid & 31;
    const int r = blockIdx.x * 8 + warp;

    const float* h = H + (long)r * FC_H + lane * 8;
    float4 v0 = *(const float4*)(h);
    float4 v1 = *(const float4*)(h + 4);
    float hv[8] = {v0.x, v0.y, v0.z, v0.w, v1.x, v1.y, v1.z, v1.w};

    float s0 = 0.f, s1 = 0.f;
#pragma unroll
    for (int i = 0; i < 8; i++) {
        const int j = lane * 8 + i;
        s0 = fmaf(hv[i], w2s[j * 2 + 0], s0);
        s1 = fmaf(hv[i], w2s[j * 2 + 1], s1);
    }
#pragma unroll
    for (int m = 16; m > 0; m >>= 1) {
        s0 += __shfl_xor_sync(0xFFFFFFFFu, s0, m);
        s1 += __shfl_xor_sync(0xFFFFFFFFu, s1, m);
    }
    if (lane == 0) {
        out[(long)r * NCLS + 0] = s0 + b2[0];
        out[(long)r * NCLS + 1] = s1 + b2[1];
    }
}

// ---------------------------------------------------------------------------
extern "C" void kernel_launch(void* const* d_in, const int* in_sizes, int n_in,
                              void* d_out, int out_size)
{
    const float* texts = (const float*)d_in[0];   // (512,32,200)
    const float* ts    = (const float*)d_in[1];   // (512,32,76)
    const float* wave  = (const float*)d_in[2];   // (32,200,1000)
    const float* wwm   = (const float*)d_in[3];   // (32,512,200)
    const float* W_wf  = (const float*)d_in[4];   // (1000,100)
    const float* b_wf  = (const float*)d_in[5];
    const float* W_ts  = (const float*)d_in[6];   // (76,256)
    const float* b_ts  = (const float*)d_in[7];
    const float* W1    = (const float*)d_in[8];   // (556,256)
    const float* b1    = (const float*)d_in[9];
    const float* W2    = (const float*)d_in[10];  // (256,2)
    const float* b2    = (const float*)d_in[11];
    float* out = (float*)d_out;

    float *C1, *P, *TS, *SP, *H;
    __nv_bfloat16* Baug;
    cudaGetSymbolAddress((void**)&C1,   g_C1);
    cudaGetSymbolAddress((void**)&P,    g_P);
    cudaGetSymbolAddress((void**)&TS,   g_TS);
    cudaGetSymbolAddress((void**)&SP,   g_SP);
    cudaGetSymbolAddress((void**)&H,    g_H);
    cudaGetSymbolAddress((void**)&Baug, g_Baug);

    const int SMEM_N128 = 4 * 128 * 80;               // 40960
    const int SMEM_N256 = 2 * 128 * 80 + 2 * 256 * 80; // 61440
    cudaFuncSetAttribute(hgemm<128, 32, 64, EPI_SCALE, false>,
                         cudaFuncAttributeMaxDynamicSharedMemorySize, SMEM_N128);
    cudaFuncSetAttribute(hgemm<256, 64, 64, EPI_TANH, false>,
                         cudaFuncAttributeMaxDynamicSharedMemorySize, SMEM_N256);
    cudaFuncSetAttribute(hgemm<256, 64, 64, EPI_RELU, true>,
                         cudaFuncAttributeMaxDynamicSharedMemorySize, SMEM_N256);

    // ---- stage 2: C1 = waveform @ W_wf + b_wf (6400 x 100 x 1000), split-K=2
    // KP3 = 1024 -> K3 = 3072 -> 96 chunks; z handles 48 chunks each.
    prep_baug<<<dim3(1536, 1), 256>>>(W_wf, WF_D, 0, WF_D, WF_LEN, 1024, 128);
    hgemm<128, 32, 64, EPI_SCALE, false><<<dim3(1, 50, 2), 256, SMEM_N128>>>(
        wave, WF_LEN, 0, nullptr, nullptr,
        Baug, 0, 1024,
        P, WF_D, (long)C1_ELEMS,
        WF_D, WF_LEN, 48, 48, nullptr, 1.f);
    reduce2_bias<<<(C1_ELEMS + 255) / 256, 256>>>(b_wf);

    // ---- stage 3: g_TS = tanh(ts @ W_ts + b_ts) (16384 x 256 x 76)
    // KP3 = 96 -> 9 chunks.
    prep_baug<<<dim3(288, 1), 256>>>(W_ts, HID, 0, HID, TS_FD, 96, 256);
    hgemm<256, 64, 64, EPI_TANH, false><<<dim3(1, 128, 1), 256, SMEM_N256>>>(
        ts, TS_FD, 0, nullptr, nullptr,
        Baug, 0, 96,
        TS, HID, 0,
        HID, TS_FD, 9, 0, b_ts, 1.f);

    // ---- stage 4: g_SP = bmm(wwm, C1) / 200 (32 x [512 x 100 x 200])
    // KP3 = 224 -> 21 chunks; z = batch.
    prep_baug<<<dim3(336, 32), 256>>>(C1, WF_D, (long)N_WF * WF_D, WF_D, N_WF, 224, 128);
    hgemm<128, 32, 64, EPI_SCALE, false><<<dim3(1, 4, 32), 256, SMEM_N128>>>(
        wwm, N_WF, (long)T_DIM * N_WF, nullptr, nullptr,
        Baug, (long)128 * 672, 224,
        SP, WF_D, (long)T_DIM * WF_D,
        WF_D, N_WF, 21, 0, nullptr, 1.f / (float)N_WF);

    // ---- stage 5: g_H = relu([texts|g_TS|g_SP] @ W1 + b1) (16384 x 256 x 556)
    // KP3 = 576 -> 54 chunks; A gathered from the three sources.
    prep_baug<<<dim3(1728, 1), 256>>>(W1, FC_H, 0, FC_H, 556, 576, 256);
    hgemm<256, 64, 64, EPI_RELU, true><<<dim3(1, 128, 1), 256, SMEM_N256>>>(
        texts, 0, 0, TS, SP,
        Baug, 0, 576,
        H, FC_H, 0,
        FC_H, 556, 54, 0, b1, 1.f);

    // ---- head: out = H @ W2 + b2 (16384 x 2 x 256)
    head_kernel<<<ROWS / 8, 256>>>(H, W2, b2, out);
}

// round 14
// speedup vs baseline: 1.6418x; 1.1436x over previous
#include <cuda_runtime.h>
#include <cuda_bf16.h>
#include <math.h>
#include <stdint.h>

// ---------------- shapes ----------------
#define T_DIM   512
#define B_DIM   32
#define TS_FD   76
#define N_WF    200
#define WF_LEN  1000
#define TEXT_D  200
#define WF_D    100
#define HID     256
#define FC_H    256
#define NCLS    2
#define ROWS    (T_DIM * B_DIM)          // 16384
#define C1_ELEMS (B_DIM * N_WF * WF_D)   // 640000

// g_Baug regions (elements)
#define OFF_WF  0L                        // 128*3072  = 393216
#define OFF_TS  393216L                   // 256*288   = 73728
#define OFF_W1  466944L                   // 256*1728  = 442368
#define OFF_B4  909312L                   // 32*128*672= 2752512  (total 3661824)

// ---------------- scratch (__device__ globals; no cudaMalloc) ----------------
__device__ float g_P[3 * C1_ELEMS];            // stage-2 split-K partials
__device__ float g_TS[ROWS * HID];             // tanh(ts proj) (16384,256)
__device__ float g_SP[ROWS * WF_D];            // spread (16384,100), rows b*512+t
__device__ __align__(16) __nv_bfloat16 g_Baug[1 << 22];  // augmented B regions

enum { EPI_TANH = 0, EPI_SCALE = 1, EPI_HEAD = 2 };

// ---------------- PTX helpers (sm_80-level: ldmatrix + HMMA bf16) ----------------
__device__ __forceinline__ uint32_t smem_u32(const void* p) {
    uint32_t a;
    asm("{ .reg .u64 t; cvta.to.shared.u64 t, %1; cvt.u32.u64 %0, t; }" : "=r"(a) : "l"(p));
    return a;
}

#define LDSM4(r0, r1, r2, r3, a) \
    asm volatile("ldmatrix.sync.aligned.m8n8.x4.shared.b16 {%0,%1,%2,%3}, [%4];" \
        : "=r"(r0), "=r"(r1), "=r"(r2), "=r"(r3) : "r"(a))

#define MMA_BF16(d, a, b) \
    asm volatile("mma.sync.aligned.m16n8k16.row.col.f32.bf16.bf16.f32 " \
        "{%0,%1,%2,%3}, {%4,%5,%6,%7}, {%8,%9}, {%0,%1,%2,%3};" \
        : "+f"((d)[0]), "+f"((d)[1]), "+f"((d)[2]), "+f"((d)[3]) \
        : "r"((a)[0]), "r"((a)[1]), "r"((a)[2]), "r"((a)[3]), \
          "r"((b)[0]), "r"((b)[1]))

// ---------------------------------------------------------------------------
// Weight prep: from fp32 src [K, N] (row stride ld) build K-augmented bf16
// [NT][3*KP3]: third0 = hi, third1 = hi, third2 = lo (pairs with A thirds
// hi, lo, hi). Zero padded (n>=N, k>=K). Writes g_Baug[dstOff + ...].
// ---------------------------------------------------------------------------
__device__ __forceinline__ void prep_one(
    const float* __restrict__ src, int ld, int N, int K, int KP3,
    long dstOff, int blk)
{
    const int idx = blk * 256 + threadIdx.x;
    const int n     = idx / (3 * KP3);
    const int ak    = idx % (3 * KP3);
    const int third = ak / KP3;
    const int k     = ak - third * KP3;
    float v = 0.f;
    if (n < N && k < K) v = src[(long)k * ld + n];
    __nv_bfloat16 h = __float2bfloat16_rn(v);
    g_Baug[dstOff + idx] =
        (third == 2) ? __float2bfloat16_rn(v - __bfloat162float(h)) : h;
}

// One launch for all three weight preps (block-range dispatch).
__global__ __launch_bounds__(256) void prep_weights(
    const float* __restrict__ W_wf, const float* __restrict__ W_ts,
    const float* __restrict__ W1)
{
    const int b = blockIdx.x;
    if (b < 1536)       prep_one(W_wf, WF_D, WF_D, WF_LEN, 1024, OFF_WF, b);
    else if (b < 1824)  prep_one(W_ts, HID,  HID,  TS_FD,  96,   OFF_TS, b - 1536);
    else                prep_one(W1,   FC_H, FC_H, 556,    576,  OFF_W1, b - 1824);
}

// ---------------------------------------------------------------------------
// Fused: stage-2 split-K(3) reduce + bias + transpose + hi/lo split, writing
// stage-4's augmented B directly: Baug4[b][d][third*224 + nwf].
// Block = (d-tile of 32, batch b). smem transpose for coalesced IO both ways.
// ---------------------------------------------------------------------------
__global__ __launch_bounds__(256) void reduce3_baug(const float* __restrict__ b_wf)
{
    __shared__ __nv_bfloat16 sH[224][36];
    __shared__ __nv_bfloat16 sL[224][36];
    const int tid = threadIdx.x;
    const int z   = blockIdx.y;           // batch
    const int d0  = blockIdx.x * 32;      // d tile

    // read phase: (nwf, d) coalesced over d
#pragma unroll 1
    for (int it = 0; it < 28; it++) {     // 224*32 / 256
        const int idx = it * 256 + tid;
        const int nwf = idx >> 5;
        const int dd  = idx & 31;
        const int d   = d0 + dd;
        float v = 0.f;
        if (nwf < N_WF && d < WF_D) {
            const long o = ((long)z * N_WF + nwf) * WF_D + d;
            v = g_P[o] + g_P[o + C1_ELEMS] + g_P[o + 2 * C1_ELEMS] + b_wf[d];
        }
        __nv_bfloat16 h = __float2bfloat16_rn(v);
        sH[nwf][dd] = h;
        sL[nwf][dd] = __float2bfloat16_rn(v - __bfloat162float(h));
    }
    __syncthreads();

    // write phase: rows d, contiguous augmented k (third*224 + nwf)
    __nv_bfloat16* dst = g_Baug + OFF_B4 + (long)z * (128 * 672) + (long)d0 * 672;
#pragma unroll 1
    for (int it = 0; it < 84; it++) {     // 32*672 / 256
        const int idx   = it * 256 + tid;
        const int dd    = idx / 672;
        const int a     = idx % 672;
        const int third = a / 224;
        const int nwf   = a - third * 224;
        dst[idx] = (third == 2) ? sL[nwf][dd] : sH[nwf][dd];
    }
}

// ---------------------------------------------------------------------------
// bf16 HMMA GEMM over the augmented K dimension (3*KP3).
// CTA: 256 threads (8 warps), tile 128 x NT, warp tile WM x WN.
// A: fp32 global -> per 32-k chunk hi-or-lo bf16 (by third) -> smem [128][40].
// B: pre-augmented bf16 [NT][3*KP3] -> smem [NT][40].
// Double buffered, register prefetch, one __syncthreads per chunk.
// GATHER: A cols from texts / g_TS / g_SP (boundaries 200/456, all /4).
// EPI_HEAD: fused relu + (256 -> 2) head GEMM + b2, writes `outp` only.
// ---------------------------------------------------------------------------
template<int NT, int WM, int WN, int EPI, bool GATHER>
__global__ __launch_bounds__(256, 1) void hgemm(
    const float* __restrict__ A, int lda, long aStr,
    const float* __restrict__ A2, const float* __restrict__ A3,
    const __nv_bfloat16* __restrict__ Baug, long bStr, int KP3,
    float* __restrict__ C, int ldc, long cStr,
    int N, int K, int NC, int zChunkOff,
    const float* __restrict__ bias, float scale,
    const float* __restrict__ W2, const float* __restrict__ b2,
    float* __restrict__ outp)
{
    extern __shared__ char smem[];
    constexpr int MI   = WM / 16;
    constexpr int NI   = WN / 8;
    constexpr int NWC  = NT / WN;
    constexpr int ABUF = 128 * 80;             // bytes per A buffer
    constexpr int BBUF = NT * 80;

    const int tid  = threadIdx.x;
    const int lane = tid & 31;
    const int wid  = tid >> 5;
    const int wr   = wid / NWC;
    const int wc   = wid % NWC;

    A    += (long)blockIdx.z * aStr;
    Baug += (long)blockIdx.z * bStr;
    C    += (long)blockIdx.z * cStr;
    const int row0g = blockIdx.y * 128;

    const uint32_t sb = smem_u32(smem);
    const uint32_t aAddr = sb +
        (((wr * WM + (lane & 15)) * 40 + ((lane >> 4) * 8)) << 1);
    const uint32_t bAddr = sb + 2 * ABUF +
        (((wc * WN + (lane & 7) + ((lane >> 4) * 8)) * 40 + (((lane >> 3) & 1) * 8)) << 1);

    float acc[MI][NI][4];
#pragma unroll
    for (int mi = 0; mi < MI; mi++)
#pragma unroll
        for (int ni = 0; ni < NI; ni++)
#pragma unroll
            for (int q = 0; q < 4; q++) acc[mi][ni][q] = 0.f;

    const int  arow = tid >> 1;
    const int  ch   = (tid & 1) * 16;
    const long rA   = row0g + arow;

    float4 va[4];
    uint4  vb[4];
    bool   aLo = false;

    auto loadA = [&](int g) {
        const int bk    = g * 32;
        const int third = bk / KP3;
        aLo = (third == 1);
        const int s0 = bk - third * KP3 + ch;
#pragma unroll
        for (int q = 0; q < 4; q++) {
            const int sc = s0 + q * 4;
            float4 f = make_float4(0.f, 0.f, 0.f, 0.f);
            if (sc < K) {
                const float* p;
                if (!GATHER)                    p = A  + rA * (long)lda    + sc;
                else if (sc < TEXT_D)           p = A  + rA * (long)TEXT_D + sc;
                else if (sc < TEXT_D + HID)     p = A2 + rA * (long)HID    + (sc - TEXT_D);
                else                            p = A3 + rA * (long)WF_D   + (sc - TEXT_D - HID);
                f = *(const float4*)p;
            }
            va[q] = f;
        }
    };
    auto storeA = [&](int buf) {
        __nv_bfloat16 hv[16];
        const float* vf = (const float*)va;
#pragma unroll
        for (int i = 0; i < 16; i++) {
            float v = vf[i];
            __nv_bfloat16 h = __float2bfloat16_rn(v);
            hv[i] = aLo ? __float2bfloat16_rn(v - __bfloat162float(h)) : h;
        }
        char* dst = smem + buf * ABUF + ((arow * 40 + ch) << 1);
        *(uint4*)dst        = *(const uint4*)&hv[0];
        *(uint4*)(dst + 16) = *(const uint4*)&hv[8];
    };
    auto loadB = [&](int g) {
        if (tid < NT) {
            const uint4* p = (const uint4*)(Baug + (long)tid * (3 * KP3) + g * 32);
            vb[0] = p[0]; vb[1] = p[1]; vb[2] = p[2]; vb[3] = p[3];
        }
    };
    auto storeB = [&](int buf) {
        if (tid < NT) {
            char* dst = smem + 2 * ABUF + buf * BBUF + tid * 80;
            *(uint4*)dst        = vb[0];
            *(uint4*)(dst + 16) = vb[1];
            *(uint4*)(dst + 32) = vb[2];
            *(uint4*)(dst + 48) = vb[3];
        }
    };

    const int g0 = blockIdx.z * zChunkOff;

    loadA(g0); loadB(g0);
    storeA(0); storeB(0);
    __syncthreads();

    for (int c = 0; c < NC; c++) {
        const int  p    = c & 1;
        const bool more = (c + 1 < NC);
        if (more) { loadA(g0 + c + 1); loadB(g0 + c + 1); }

#pragma unroll
        for (int kk = 0; kk < 2; kk++) {
            uint32_t af[MI][4];
#pragma unroll
            for (int mi = 0; mi < MI; mi++)
                LDSM4(af[mi][0], af[mi][1], af[mi][2], af[mi][3],
                      aAddr + p * ABUF + mi * (16 * 80) + kk * 32);
            uint32_t bfr[NI][2];
#pragma unroll
            for (int nb = 0; nb < NI / 2; nb++)
                LDSM4(bfr[2 * nb][0], bfr[2 * nb][1], bfr[2 * nb + 1][0], bfr[2 * nb + 1][1],
                      bAddr + p * BBUF + nb * (16 * 80) + kk * 32);
#pragma unroll
            for (int mi = 0; mi < MI; mi++)
#pragma unroll
                for (int ni = 0; ni < NI; ni++)
                    MMA_BF16(acc[mi][ni], af[mi], bfr[ni]);
        }

        if (more) { storeA(p ^ 1); storeB(p ^ 1); }
        __syncthreads();
    }

    // ---- epilogue: fragment (r = l/4 [+8], c = (l%4)*2) ----
    const int rw = row0g + wr * WM + (lane >> 2);
    const int cw = wc * WN + (lane & 3) * 2;

    if (EPI == EPI_HEAD) {
        // fused relu + head: s[mi][pair][cls]
        float s[MI][2][2];
#pragma unroll
        for (int mi = 0; mi < MI; mi++)
#pragma unroll
            for (int pr = 0; pr < 2; pr++) { s[mi][pr][0] = 0.f; s[mi][pr][1] = 0.f; }
#pragma unroll
        for (int mi = 0; mi < MI; mi++) {
#pragma unroll
            for (int ni = 0; ni < NI; ni++) {
                const int col = cw + ni * 8;
                const float b0 = bias[col], b1v = bias[col + 1];
                const float w00 = W2[col * 2 + 0], w01 = W2[col * 2 + 1];
                const float w10 = W2[col * 2 + 2], w11 = W2[col * 2 + 3];
                float v0 = acc[mi][ni][0] + b0;  v0 = v0 > 0.f ? v0 : 0.f;
                float v1 = acc[mi][ni][1] + b1v; v1 = v1 > 0.f ? v1 : 0.f;
                float v2 = acc[mi][ni][2] + b0;  v2 = v2 > 0.f ? v2 : 0.f;
                float v3 = acc[mi][ni][3] + b1v; v3 = v3 > 0.f ? v3 : 0.f;
                s[mi][0][0] = fmaf(v0, w00, fmaf(v1, w10, s[mi][0][0]));
                s[mi][0][1] = fmaf(v0, w01, fmaf(v1, w11, s[mi][0][1]));
                s[mi][1][0] = fmaf(v2, w00, fmaf(v3, w10, s[mi][1][0]));
                s[mi][1][1] = fmaf(v2, w01, fmaf(v3, w11, s[mi][1][1]));
            }
        }
        // reduce over the 4 lanes sharing the same rows (lane&3 = col group)
#pragma unroll
        for (int mi = 0; mi < MI; mi++)
#pragma unroll
            for (int pr = 0; pr < 2; pr++)
#pragma unroll
                for (int cl = 0; cl < 2; cl++) {
                    float v = s[mi][pr][cl];
                    v += __shfl_xor_sync(0xFFFFFFFFu, v, 1);
                    v += __shfl_xor_sync(0xFFFFFFFFu, v, 2);
                    s[mi][pr][cl] = v;
                }
        // cross-warp (wc) reduce via smem: red[wc][128][2]  (aliases A buffers)
        float* red = (float*)smem;
        if ((lane & 3) == 0) {
            const int rbase = wr * WM + (lane >> 2);
#pragma unroll
            for (int mi = 0; mi < MI; mi++)
#pragma unroll
                for (int pr = 0; pr < 2; pr++) {
                    const int row = rbase + mi * 16 + pr * 8;
                    red[(wc * 128 + row) * 2 + 0] = s[mi][pr][0];
                    red[(wc * 128 + row) * 2 + 1] = s[mi][pr][1];
                }
        }
        __syncthreads();
        {
            const int row = tid >> 1;
            const int cl  = tid & 1;
            float v = red[(0 * 128 + row) * 2 + cl] + red[(1 * 128 + row) * 2 + cl]
                    + red[(2 * 128 + row) * 2 + cl] + red[(3 * 128 + row) * 2 + cl]
                    + b2[cl];
            outp[(long)(row0g + row) * 2 + cl] = v;
        }
        return;
    }

#pragma unroll
    for (int mi = 0; mi < MI; mi++) {
#pragma unroll
        for (int ni = 0; ni < NI; ni++) {
            const int col = cw + ni * 8;
            if (col < N) {
                float v0 = acc[mi][ni][0], v1 = acc[mi][ni][1];
                float v2 = acc[mi][ni][2], v3 = acc[mi][ni][3];
                if (EPI == EPI_TANH) {
                    const float b0 = bias[col], b1v = bias[col + 1];
                    v0 = tanhf(v0 + b0); v1 = tanhf(v1 + b1v);
                    v2 = tanhf(v2 + b0); v3 = tanhf(v3 + b1v);
                } else {  // SCALE
                    v0 *= scale; v1 *= scale; v2 *= scale; v3 *= scale;
                }
                const int r1 = rw + mi * 16;
                *(float2*)(C + (long)r1 * ldc + col)       = make_float2(v0, v1);
                *(float2*)(C + (long)(r1 + 8) * ldc + col) = make_float2(v2, v3);
            }
        }
    }
}

// ---------------------------------------------------------------------------
extern "C" void kernel_launch(void* const* d_in, const int* in_sizes, int n_in,
                              void* d_out, int out_size)
{
    const float* texts = (const float*)d_in[0];   // (512,32,200)
    const float* ts    = (const float*)d_in[1];   // (512,32,76)
    const float* wave  = (const float*)d_in[2];   // (32,200,1000)
    const float* wwm   = (const float*)d_in[3];   // (32,512,200)
    const float* W_wf  = (const float*)d_in[4];   // (1000,100)
    const float* b_wf  = (const float*)d_in[5];
    const float* W_ts  = (const float*)d_in[6];   // (76,256)
    const float* b_ts  = (const float*)d_in[7];
    const float* W1    = (const float*)d_in[8];   // (556,256)
    const float* b1    = (const float*)d_in[9];
    const float* W2    = (const float*)d_in[10];  // (256,2)
    const float* b2    = (const float*)d_in[11];
    float* out = (float*)d_out;

    float *P, *TS, *SP;
    __nv_bfloat16* Baug;
    cudaGetSymbolAddress((void**)&P,    g_P);
    cudaGetSymbolAddress((void**)&TS,   g_TS);
    cudaGetSymbolAddress((void**)&SP,   g_SP);
    cudaGetSymbolAddress((void**)&Baug, g_Baug);

    const int SMEM_N128 = 4 * 128 * 80;                 // 40960
    const int SMEM_N256 = 2 * 128 * 80 + 2 * 256 * 80;  // 61440
    cudaFuncSetAttribute(hgemm<128, 32, 64, EPI_SCALE, false>,
                         cudaFuncAttributeMaxDynamicSharedMemorySize, SMEM_N128);
    cudaFuncSetAttribute(hgemm<256, 64, 64, EPI_TANH, false>,
                         cudaFuncAttributeMaxDynamicSharedMemorySize, SMEM_N256);
    cudaFuncSetAttribute(hgemm<256, 64, 64, EPI_HEAD, true>,
                         cudaFuncAttributeMaxDynamicSharedMemorySize, SMEM_N256);

    // 1) all weight preps in one launch
    prep_weights<<<3552, 256>>>(W_wf, W_ts, W1);

    // 2) stage 2: P[kz] = partial(waveform @ W_wf), split-K=3 (KP3=1024 -> 96
    //    chunks, 32 per z). 150 CTAs.
    hgemm<128, 32, 64, EPI_SCALE, false><<<dim3(1, 50, 3), 256, SMEM_N128>>>(
        wave, WF_LEN, 0, nullptr, nullptr,
        Baug + OFF_WF, 0, 1024,
        P, WF_D, (long)C1_ELEMS,
        WF_D, WF_LEN, 32, 32, nullptr, 1.f, nullptr, nullptr, nullptr);

    // 3) stage 3: g_TS = tanh(ts @ W_ts + b_ts)  (KP3=96 -> 9 chunks)
    hgemm<256, 64, 64, EPI_TANH, false><<<dim3(1, 128, 1), 256, SMEM_N256>>>(
        ts, TS_FD, 0, nullptr, nullptr,
        Baug + OFF_TS, 0, 96,
        TS, HID, 0,
        HID, TS_FD, 9, 0, b_ts, 1.f, nullptr, nullptr, nullptr);

    // 4) fused reduce(3 partials)+bias -> stage-4 augmented B (hi,hi,lo)
    reduce3_baug<<<dim3(4, 32), 256>>>(b_wf);

    // 5) stage 4: g_SP = bmm(wwm, wf_out) / 200  (KP3=224 -> 21 chunks; z=batch)
    hgemm<128, 32, 64, EPI_SCALE, false><<<dim3(1, 4, 32), 256, SMEM_N128>>>(
        wwm, N_WF, (long)T_DIM * N_WF, nullptr, nullptr,
        Baug + OFF_B4, (long)128 * 672, 224,
        SP, WF_D, (long)T_DIM * WF_D,
        WF_D, N_WF, 21, 0, nullptr, 1.f / (float)N_WF, nullptr, nullptr, nullptr);

    // 6) stage 5 + head fused:
    //    out = relu([texts|g_TS|g_SP] @ W1 + b1) @ W2 + b2  (KP3=576 -> 54 chunks)
    hgemm<256, 64, 64, EPI_HEAD, true><<<dim3(1, 128, 1), 256, SMEM_N256>>>(
        texts, 0, 0, TS, SP,
        Baug + OFF_W1, 0, 576,
        out, 0, 0,
        FC_H, 556, 54, 0, b1, 1.f, W2, b2, out);
}

// round 15
// speedup vs baseline: 1.7824x; 1.0856x over previous
#include <cuda_runtime.h>
#include <cuda_bf16.h>
#include <math.h>
#include <stdint.h>

// ---------------- shapes ----------------
#define T_DIM   512
#define B_DIM   32
#define TS_FD   76
#define N_WF    200
#define WF_LEN  1000
#define TEXT_D  200
#define WF_D    100
#define HID     256
#define FC_H    256
#define NCLS    2
#define ROWS    (T_DIM * B_DIM)          // 16384
#define C1_ELEMS (B_DIM * N_WF * WF_D)   // 640000

// g_Baug regions (elements)
#define OFF_WF  0L                        // 128*3072  = 393216
#define OFF_TS  393216L                   // 256*288   = 73728
#define OFF_W1  466944L                   // 256*1728  = 442368
#define OFF_B4  909312L                   // 32*128*672= 2752512  (total 3661824)

// ---------------- scratch (__device__ globals; no cudaMalloc) ----------------
__device__ float g_P[3 * C1_ELEMS];            // stage-2 split-K partials
__device__ float g_TS[ROWS * HID];             // tanh(ts proj) (16384,256)
__device__ float g_SP[ROWS * WF_D];            // spread (16384,100), rows b*512+t
__device__ __align__(16) __nv_bfloat16 g_Baug[1 << 22];  // augmented B regions

enum { EPI_TANH = 0, EPI_SCALE = 1, EPI_HEAD = 2 };

// ---------------- PTX helpers (sm_80-level: ldmatrix + HMMA bf16) ----------------
__device__ __forceinline__ uint32_t smem_u32(const void* p) {
    uint32_t a;
    asm("{ .reg .u64 t; cvta.to.shared.u64 t, %1; cvt.u32.u64 %0, t; }" : "=r"(a) : "l"(p));
    return a;
}

#define LDSM4(r0, r1, r2, r3, a) \
    asm volatile("ldmatrix.sync.aligned.m8n8.x4.shared.b16 {%0,%1,%2,%3}, [%4];" \
        : "=r"(r0), "=r"(r1), "=r"(r2), "=r"(r3) : "r"(a))

#define MMA_BF16(d, a, b) \
    asm volatile("mma.sync.aligned.m16n8k16.row.col.f32.bf16.bf16.f32 " \
        "{%0,%1,%2,%3}, {%4,%5,%6,%7}, {%8,%9}, {%0,%1,%2,%3};" \
        : "+f"((d)[0]), "+f"((d)[1]), "+f"((d)[2]), "+f"((d)[3]) \
        : "r"((a)[0]), "r"((a)[1]), "r"((a)[2]), "r"((a)[3]), \
          "r"((b)[0]), "r"((b)[1]))

// ---------------------------------------------------------------------------
// Tiled weight prep: 32x32 smem transpose per block.
// src fp32 [K, N] (row stride ld); dst = g_Baug[dstOff] as [NT][3*KP3] with
// thirds hi, hi, lo (pairs with A thirds hi, lo, hi). Zero padding for
// k >= K, n >= N. Reads coalesced over n; writes 64B runs over k.
// One launch covers all three weights via linear block dispatch.
// ---------------------------------------------------------------------------
__device__ __forceinline__ void prep_tile(
    const float* __restrict__ src, int ld, int N, int K, int KP3,
    long dstOff, int kt, int nt)
{
    __shared__ float s[32][33];
    const int tid = threadIdx.x;
    const int k0 = kt * 32, n0 = nt * 32;

    // read: thread (j = tid&31, rows i = (tid>>5)*4 .. +3), coalesced over n
    const int j = tid & 31;
    const int i0 = (tid >> 5) * 4;
#pragma unroll
    for (int r = 0; r < 4; r++) {
        const int k = k0 + i0 + r;
        const int n = n0 + j;
        s[i0 + r][j] = (k < K && n < N) ? src[(long)k * ld + n] : 0.f;
    }
    __syncthreads();

    // write: thread (n = tid>>3, kq = (tid&7)*4), 8B per write, runs of 64B
    const int n = tid >> 3;
    const int kq = (tid & 7) * 4;
    float v[4];
    __nv_bfloat16 hv[4], lv[4];
#pragma unroll
    for (int q = 0; q < 4; q++) {
        v[q]  = s[kq + q][n];
        hv[q] = __float2bfloat16_rn(v[q]);
        lv[q] = __float2bfloat16_rn(v[q] - __bfloat162float(hv[q]));
    }
    __nv_bfloat16* row = g_Baug + dstOff + (long)(n0 + n) * (3 * KP3) + k0 + kq;
    *(uint2*)(row)           = *(const uint2*)hv;   // third 0: hi
    *(uint2*)(row + KP3)     = *(const uint2*)hv;   // third 1: hi
    *(uint2*)(row + 2 * KP3) = *(const uint2*)lv;   // third 2: lo
}

// W_wf: 32 k-tiles x 4 n-tiles = 128 | W_ts: 3 x 8 = 24 | W1: 18 x 8 = 144
__global__ __launch_bounds__(256) void prep_weights(
    const float* __restrict__ W_wf, const float* __restrict__ W_ts,
    const float* __restrict__ W1)
{
    const int b = blockIdx.x;
    if (b < 128)       prep_tile(W_wf, WF_D, WF_D, WF_LEN, 1024, OFF_WF, b & 31, b >> 5);
    else if (b < 152)  { const int t = b - 128; prep_tile(W_ts, HID, HID, TS_FD, 96,  OFF_TS, t % 3,  t / 3); }
    else               { const int t = b - 152; prep_tile(W1,   FC_H, FC_H, 556,  576, OFF_W1, t % 18, t / 18); }
}

// ---------------------------------------------------------------------------
// Fused stage-2 reduce(3 partials) + bias + transpose + hi/lo split into the
// stage-4 augmented B: Baug4[z][d][third*224 + nwf].  32x32 smem tiles.
// grid = (7 nwf-tiles, 4 d-tiles, 32 z).  Reads coalesced over d (contiguous
// in g_P); writes 64B nwf-runs per (d, third).
// ---------------------------------------------------------------------------
__global__ __launch_bounds__(256) void reduce3_baug(const float* __restrict__ b_wf)
{
    __shared__ float s[32][33];          // [nwf][d]
    const int tid = threadIdx.x;
    const int w0 = blockIdx.x * 32;      // nwf tile (0..192)
    const int d0 = blockIdx.y * 32;      // d tile (0..96; d >= 100 padded)
    const int z  = blockIdx.z;

    const int j  = tid & 31;             // d lane
    const int i0 = (tid >> 5) * 4;       // nwf rows
    const int d  = d0 + j;
    const float bias = (d < WF_D) ? b_wf[d] : 0.f;
#pragma unroll
    for (int r = 0; r < 4; r++) {
        const int nwf = w0 + i0 + r;
        float v = 0.f;
        if (nwf < N_WF && d < WF_D) {
            const long o = ((long)z * N_WF + nwf) * WF_D + d;
            v = g_P[o] + g_P[o + C1_ELEMS] + g_P[o + 2 * C1_ELEMS] + bias;
        }
        s[i0 + r][j] = v;
    }
    __syncthreads();

    const int dn = tid >> 3;             // d row within tile
    const int wq = (tid & 7) * 4;        // nwf quad
    __nv_bfloat16 hv[4], lv[4];
#pragma unroll
    for (int q = 0; q < 4; q++) {
        const float v = s[wq + q][dn];
        hv[q] = __float2bfloat16_rn(v);
        lv[q] = __float2bfloat16_rn(v - __bfloat162float(hv[q]));
    }
    __nv_bfloat16* row = g_Baug + OFF_B4 + (long)z * (128 * 672)
                       + (long)(d0 + dn) * 672 + w0 + wq;
    *(uint2*)(row)           = *(const uint2*)hv;   // third 0: hi
    *(uint2*)(row + 224)     = *(const uint2*)hv;   // third 1: hi
    *(uint2*)(row + 448)     = *(const uint2*)lv;   // third 2: lo
}

// ---------------------------------------------------------------------------
// bf16 HMMA GEMM over the augmented K dimension (3*KP3).
// CTA: 256 threads (8 warps), tile 128 x NT, warp tile WM x WN.
// A: fp32 global -> per 32-k chunk hi-or-lo bf16 (by third) -> smem [128][40].
// B: pre-augmented bf16 [NT][3*KP3] -> smem [NT][40].
// Double buffered, register prefetch, one __syncthreads per chunk.
// GATHER: A cols from texts / g_TS / g_SP (boundaries 200/456, all /4).
// EPI_HEAD: fused relu + (256 -> 2) head GEMM + b2, writes `outp` only.
// ---------------------------------------------------------------------------
template<int NT, int WM, int WN, int EPI, bool GATHER>
__global__ __launch_bounds__(256, 1) void hgemm(
    const float* __restrict__ A, int lda, long aStr,
    const float* __restrict__ A2, const float* __restrict__ A3,
    const __nv_bfloat16* __restrict__ Baug, long bStr, int KP3,
    float* __restrict__ C, int ldc, long cStr,
    int N, int K, int NC, int zChunkOff,
    const float* __restrict__ bias, float scale,
    const float* __restrict__ W2, const float* __restrict__ b2,
    float* __restrict__ outp)
{
    extern __shared__ char smem[];
    constexpr int MI   = WM / 16;
    constexpr int NI   = WN / 8;
    constexpr int NWC  = NT / WN;
    constexpr int ABUF = 128 * 80;             // bytes per A buffer
    constexpr int BBUF = NT * 80;

    const int tid  = threadIdx.x;
    const int lane = tid & 31;
    const int wid  = tid >> 5;
    const int wr   = wid / NWC;
    const int wc   = wid % NWC;

    A    += (long)blockIdx.z * aStr;
    Baug += (long)blockIdx.z * bStr;
    C    += (long)blockIdx.z * cStr;
    const int row0g = blockIdx.y * 128;

    const uint32_t sb = smem_u32(smem);
    const uint32_t aAddr = sb +
        (((wr * WM + (lane & 15)) * 40 + ((lane >> 4) * 8)) << 1);
    const uint32_t bAddr = sb + 2 * ABUF +
        (((wc * WN + (lane & 7) + ((lane >> 4) * 8)) * 40 + (((lane >> 3) & 1) * 8)) << 1);

    float acc[MI][NI][4];
#pragma unroll
    for (int mi = 0; mi < MI; mi++)
#pragma unroll
        for (int ni = 0; ni < NI; ni++)
#pragma unroll
            for (int q = 0; q < 4; q++) acc[mi][ni][q] = 0.f;

    const int  arow = tid >> 1;
    const int  ch   = (tid & 1) * 16;
    const long rA   = row0g + arow;

    float4 va[4];
    uint4  vb[4];
    bool   aLo = false;

    auto loadA = [&](int g) {
        const int bk    = g * 32;
        const int third = bk / KP3;
        aLo = (third == 1);
        const int s0 = bk - third * KP3 + ch;
#pragma unroll
        for (int q = 0; q < 4; q++) {
            const int sc = s0 + q * 4;
            float4 f = make_float4(0.f, 0.f, 0.f, 0.f);
            if (sc < K) {
                const float* p;
                if (!GATHER)                    p = A  + rA * (long)lda    + sc;
                else if (sc < TEXT_D)           p = A  + rA * (long)TEXT_D + sc;
                else if (sc < TEXT_D + HID)     p = A2 + rA * (long)HID    + (sc - TEXT_D);
                else                            p = A3 + rA * (long)WF_D   + (sc - TEXT_D - HID);
                f = *(const float4*)p;
            }
            va[q] = f;
        }
    };
    auto storeA = [&](int buf) {
        __nv_bfloat16 hv[16];
        const float* vf = (const float*)va;
#pragma unroll
        for (int i = 0; i < 16; i++) {
            float v = vf[i];
            __nv_bfloat16 h = __float2bfloat16_rn(v);
            hv[i] = aLo ? __float2bfloat16_rn(v - __bfloat162float(h)) : h;
        }
        char* dst = smem + buf * ABUF + ((arow * 40 + ch) << 1);
        *(uint4*)dst        = *(const uint4*)&hv[0];
        *(uint4*)(dst + 16) = *(const uint4*)&hv[8];
    };
    auto loadB = [&](int g) {
        if (tid < NT) {
            const uint4* p = (const uint4*)(Baug + (long)tid * (3 * KP3) + g * 32);
            vb[0] = p[0]; vb[1] = p[1]; vb[2] = p[2]; vb[3] = p[3];
        }
    };
    auto storeB = [&](int buf) {
        if (tid < NT) {
            char* dst = smem + 2 * ABUF + buf * BBUF + tid * 80;
            *(uint4*)dst        = vb[0];
            *(uint4*)(dst + 16) = vb[1];
            *(uint4*)(dst + 32) = vb[2];
            *(uint4*)(dst + 48) = vb[3];
        }
    };

    const int g0 = blockIdx.z * zChunkOff;

    loadA(g0); loadB(g0);
    storeA(0); storeB(0);
    __syncthreads();

    for (int c = 0; c < NC; c++) {
        const int  p    = c & 1;
        const bool more = (c + 1 < NC);
        if (more) { loadA(g0 + c + 1); loadB(g0 + c + 1); }

#pragma unroll
        for (int kk = 0; kk < 2; kk++) {
            uint32_t af[MI][4];
#pragma unroll
            for (int mi = 0; mi < MI; mi++)
                LDSM4(af[mi][0], af[mi][1], af[mi][2], af[mi][3],
                      aAddr + p * ABUF + mi * (16 * 80) + kk * 32);
            uint32_t bfr[NI][2];
#pragma unroll
            for (int nb = 0; nb < NI / 2; nb++)
                LDSM4(bfr[2 * nb][0], bfr[2 * nb][1], bfr[2 * nb + 1][0], bfr[2 * nb + 1][1],
                      bAddr + p * BBUF + nb * (16 * 80) + kk * 32);
#pragma unroll
            for (int mi = 0; mi < MI; mi++)
#pragma unroll
                for (int ni = 0; ni < NI; ni++)
                    MMA_BF16(acc[mi][ni], af[mi], bfr[ni]);
        }

        if (more) { storeA(p ^ 1); storeB(p ^ 1); }
        __syncthreads();
    }

    // ---- epilogue: fragment (r = l/4 [+8], c = (l%4)*2) ----
    const int rw = row0g + wr * WM + (lane >> 2);
    const int cw = wc * WN + (lane & 3) * 2;

    if (EPI == EPI_HEAD) {
        // fused relu + head: s[mi][pair][cls]
        float s[MI][2][2];
#pragma unroll
        for (int mi = 0; mi < MI; mi++)
#pragma unroll
            for (int pr = 0; pr < 2; pr++) { s[mi][pr][0] = 0.f; s[mi][pr][1] = 0.f; }
#pragma unroll
        for (int mi = 0; mi < MI; mi++) {
#pragma unroll
            for (int ni = 0; ni < NI; ni++) {
                const int col = cw + ni * 8;
                const float b0 = bias[col], b1v = bias[col + 1];
                const float w00 = W2[col * 2 + 0], w01 = W2[col * 2 + 1];
                const float w10 = W2[col * 2 + 2], w11 = W2[col * 2 + 3];
                float v0 = acc[mi][ni][0] + b0;  v0 = v0 > 0.f ? v0 : 0.f;
                float v1 = acc[mi][ni][1] + b1v; v1 = v1 > 0.f ? v1 : 0.f;
                float v2 = acc[mi][ni][2] + b0;  v2 = v2 > 0.f ? v2 : 0.f;
                float v3 = acc[mi][ni][3] + b1v; v3 = v3 > 0.f ? v3 : 0.f;
                s[mi][0][0] = fmaf(v0, w00, fmaf(v1, w10, s[mi][0][0]));
                s[mi][0][1] = fmaf(v0, w01, fmaf(v1, w11, s[mi][0][1]));
                s[mi][1][0] = fmaf(v2, w00, fmaf(v3, w10, s[mi][1][0]));
                s[mi][1][1] = fmaf(v2, w01, fmaf(v3, w11, s[mi][1][1]));
            }
        }
        // reduce over the 4 lanes sharing the same rows (lane&3 = col group)
#pragma unroll
        for (int mi = 0; mi < MI; mi++)
#pragma unroll
            for (int pr = 0; pr < 2; pr++)
#pragma unroll
                for (int cl = 0; cl < 2; cl++) {
                    float v = s[mi][pr][cl];
                    v += __shfl_xor_sync(0xFFFFFFFFu, v, 1);
                    v += __shfl_xor_sync(0xFFFFFFFFu, v, 2);
                    s[mi][pr][cl] = v;
                }
        // cross-warp (wc) reduce via smem: red[wc][128][2]  (aliases A buffers)
        float* red = (float*)smem;
        __syncthreads();
        if ((lane & 3) == 0) {
            const int rbase = wr * WM + (lane >> 2);
#pragma unroll
            for (int mi = 0; mi < MI; mi++)
#pragma unroll
                for (int pr = 0; pr < 2; pr++) {
                    const int row = rbase + mi * 16 + pr * 8;
                    red[(wc * 128 + row) * 2 + 0] = s[mi][pr][0];
                    red[(wc * 128 + row) * 2 + 1] = s[mi][pr][1];
                }
        }
        __syncthreads();
        {
            const int row = tid >> 1;
            const int cl  = tid & 1;
            float v = red[(0 * 128 + row) * 2 + cl] + red[(1 * 128 + row) * 2 + cl]
                    + red[(2 * 128 + row) * 2 + cl] + red[(3 * 128 + row) * 2 + cl]
                    + b2[cl];
            outp[(long)(row0g + row) * 2 + cl] = v;
        }
        return;
    }

#pragma unroll
    for (int mi = 0; mi < MI; mi++) {
#pragma unroll
        for (int ni = 0; ni < NI; ni++) {
            const int col = cw + ni * 8;
            if (col < N) {
                float v0 = acc[mi][ni][0], v1 = acc[mi][ni][1];
                float v2 = acc[mi][ni][2], v3 = acc[mi][ni][3];
                if (EPI == EPI_TANH) {
                    const float b0 = bias[col], b1v = bias[col + 1];
                    v0 = tanhf(v0 + b0); v1 = tanhf(v1 + b1v);
                    v2 = tanhf(v2 + b0); v3 = tanhf(v3 + b1v);
                } else {  // SCALE
                    v0 *= scale; v1 *= scale; v2 *= scale; v3 *= scale;
                }
                const int r1 = rw + mi * 16;
                *(float2*)(C + (long)r1 * ldc + col)       = make_float2(v0, v1);
                *(float2*)(C + (long)(r1 + 8) * ldc + col) = make_float2(v2, v3);
            }
        }
    }
}

// ---------------------------------------------------------------------------
extern "C" void kernel_launch(void* const* d_in, const int* in_sizes, int n_in,
                              void* d_out, int out_size)
{
    const float* texts = (const float*)d_in[0];   // (512,32,200)
    const float* ts    = (const float*)d_in[1];   // (512,32,76)
    const float* wave  = (const float*)d_in[2];   // (32,200,1000)
    const float* wwm   = (const float*)d_in[3];   // (32,512,200)
    const float* W_wf  = (const float*)d_in[4];   // (1000,100)
    const float* b_wf  = (const float*)d_in[5];
    const float* W_ts  = (const float*)d_in[6];   // (76,256)
    const float* b_ts  = (const float*)d_in[7];
    const float* W1    = (const float*)d_in[8];   // (556,256)
    const float* b1    = (const float*)d_in[9];
    const float* W2    = (const float*)d_in[10];  // (256,2)
    const float* b2    = (const float*)d_in[11];
    float* out = (float*)d_out;

    float *P, *TS, *SP;
    __nv_bfloat16* Baug;
    cudaGetSymbolAddress((void**)&P,    g_P);
    cudaGetSymbolAddress((void**)&TS,   g_TS);
    cudaGetSymbolAddress((void**)&SP,   g_SP);
    cudaGetSymbolAddress((void**)&Baug, g_Baug);

    const int SMEM_N128 = 4 * 128 * 80;                 // 40960
    const int SMEM_N256 = 2 * 128 * 80 + 2 * 256 * 80;  // 61440
    cudaFuncSetAttribute(hgemm<128, 32, 64, EPI_SCALE, false>,
                         cudaFuncAttributeMaxDynamicSharedMemorySize, SMEM_N128);
    cudaFuncSetAttribute(hgemm<256, 64, 64, EPI_TANH, false>,
                         cudaFuncAttributeMaxDynamicSharedMemorySize, SMEM_N256);
    cudaFuncSetAttribute(hgemm<256, 64, 64, EPI_HEAD, true>,
                         cudaFuncAttributeMaxDynamicSharedMemorySize, SMEM_N256);

    // 1) all weight preps, tiled transpose, one launch (128 + 24 + 144 blocks)
    prep_weights<<<296, 256>>>(W_wf, W_ts, W1);

    // 2) stage 2: P[kz] = partial(waveform @ W_wf), split-K=3 (KP3=1024 -> 96
    //    chunks, 32 per z). 150 CTAs.
    hgemm<128, 32, 64, EPI_SCALE, false><<<dim3(1, 50, 3), 256, SMEM_N128>>>(
        wave, WF_LEN, 0, nullptr, nullptr,
        Baug + OFF_WF, 0, 1024,
        P, WF_D, (long)C1_ELEMS,
        WF_D, WF_LEN, 32, 32, nullptr, 1.f, nullptr, nullptr, nullptr);

    // 3) stage 3: g_TS = tanh(ts @ W_ts + b_ts)  (KP3=96 -> 9 chunks)
    hgemm<256, 64, 64, EPI_TANH, false><<<dim3(1, 128, 1), 256, SMEM_N256>>>(
        ts, TS_FD, 0, nullptr, nullptr,
        Baug + OFF_TS, 0, 96,
        TS, HID, 0,
        HID, TS_FD, 9, 0, b_ts, 1.f, nullptr, nullptr, nullptr);

    // 4) fused reduce(3 partials)+bias -> stage-4 augmented B (tiled transpose)
    reduce3_baug<<<dim3(7, 4, 32), 256>>>(b_wf);

    // 5) stage 4: g_SP = bmm(wwm, wf_out) / 200  (KP3=224 -> 21 chunks; z=batch)
    hgemm<128, 32, 64, EPI_SCALE, false><<<dim3(1, 4, 32), 256, SMEM_N128>>>(
        wwm, N_WF, (long)T_DIM * N_WF, nullptr, nullptr,
        Baug + OFF_B4, (long)128 * 672, 224,
        SP, WF_D, (long)T_DIM * WF_D,
        WF_D, N_WF, 21, 0, nullptr, 1.f / (float)N_WF, nullptr, nullptr, nullptr);

    // 6) stage 5 + head fused:
    //    out = relu([texts|g_TS|g_SP] @ W1 + b1) @ W2 + b2  (KP3=576 -> 54 chunks)
    hgemm<256, 64, 64, EPI_HEAD, true><<<dim3(1, 128, 1), 256, SMEM_N256>>>(
        texts, 0, 0, TS, SP,
        Baug + OFF_W1, 0, 576,
        out, 0, 0,
        FC_H, 556, 54, 0, b1, 1.f, W2, b2, out);
}

// round 16
// speedup vs baseline: 2.5738x; 1.4440x over previous
#include <cuda_runtime.h>
#include <cuda_bf16.h>
#include <math.h>
#include <stdint.h>

// ---------------- shapes ----------------
#define T_DIM   512
#define B_DIM   32
#define TS_FD   76
#define N_WF    200
#define WF_LEN  1000
#define TEXT_D  200
#define WF_D    100
#define HID     256
#define FC_H    256
#define NCLS    2
#define ROWS    (T_DIM * B_DIM)          // 16384
#define C1_ELEMS (B_DIM * N_WF * WF_D)   // 640000

// g_Baug regions (elements). Layout per row: [2*KP3], each 32-block = [hi32|lo32]
#define OFF_WF  0L                        // 128 * 2048 = 262144
#define OFF_TS  262144L                   // 256 * 192  = 49152
#define OFF_W1  311296L                   // 256 * 1152 = 294912
#define OFF_B4  606208L                   // 32*128*448 = 1835008 (total 2441216)

// ---------------- scratch (__device__ globals; no cudaMalloc) ----------------
__device__ float g_P[4 * C1_ELEMS];            // stage-2 split-K partials
__device__ float g_TS[ROWS * HID];             // tanh(ts proj) (16384,256)
__device__ float g_SP[ROWS * WF_D];            // spread (16384,100), rows b*512+t
__device__ __align__(16) __nv_bfloat16 g_Baug[1 << 22];  // hi/lo-interleaved B

enum { EPI_TANH = 0, EPI_SCALE = 1, EPI_HEAD = 2 };

// ---------------- PTX helpers (sm_80-level: ldmatrix + HMMA bf16) ----------------
__device__ __forceinline__ uint32_t smem_u32(const void* p) {
    uint32_t a;
    asm("{ .reg .u64 t; cvta.to.shared.u64 t, %1; cvt.u32.u64 %0, t; }" : "=r"(a) : "l"(p));
    return a;
}

#define LDSM4(r0, r1, r2, r3, a) \
    asm volatile("ldmatrix.sync.aligned.m8n8.x4.shared.b16 {%0,%1,%2,%3}, [%4];" \
        : "=r"(r0), "=r"(r1), "=r"(r2), "=r"(r3) : "r"(a))

#define MMA_BF16(d, a, b) \
    asm volatile("mma.sync.aligned.m16n8k16.row.col.f32.bf16.bf16.f32 " \
        "{%0,%1,%2,%3}, {%4,%5,%6,%7}, {%8,%9}, {%0,%1,%2,%3};" \
        : "+f"((d)[0]), "+f"((d)[1]), "+f"((d)[2]), "+f"((d)[3]) \
        : "r"((a)[0]), "r"((a)[1]), "r"((a)[2]), "r"((a)[3]), \
          "r"((b)[0]), "r"((b)[1]))

// ---------------------------------------------------------------------------
// Tiled weight prep: 32x32 smem transpose per block.
// src fp32 [K, N] (row stride ld); dst rows [NT][2*KP3]: block b at b*64,
// hi32 then lo32.  Zero padded (k >= K, n >= N).
// ---------------------------------------------------------------------------
__device__ __forceinline__ void prep_tile(
    const float* __restrict__ src, int ld, int N, int K, int KP3,
    long dstOff, int kt, int nt)
{
    __shared__ float s[32][33];
    const int tid = threadIdx.x;
    const int k0 = kt * 32, n0 = nt * 32;

    const int j  = tid & 31;
    const int i0 = (tid >> 5) * 4;
#pragma unroll
    for (int r = 0; r < 4; r++) {
        const int k = k0 + i0 + r;
        const int n = n0 + j;
        s[i0 + r][j] = (k < K && n < N) ? src[(long)k * ld + n] : 0.f;
    }
    __syncthreads();

    const int n  = tid >> 3;
    const int kq = (tid & 7) * 4;
    __nv_bfloat16 hv[4], lv[4];
#pragma unroll
    for (int q = 0; q < 4; q++) {
        const float v = s[kq + q][n];
        hv[q] = __float2bfloat16_rn(v);
        lv[q] = __float2bfloat16_rn(v - __bfloat162float(hv[q]));
    }
    __nv_bfloat16* row = g_Baug + dstOff + (long)(n0 + n) * (2 * KP3) + kt * 64 + kq;
    *(uint2*)(row)      = *(const uint2*)hv;   // hi
    *(uint2*)(row + 32) = *(const uint2*)lv;   // lo
}

// W_wf: 32 k-tiles x 4 n-tiles = 128 | W_ts: 3 x 8 = 24 | W1: 18 x 8 = 144
__global__ __launch_bounds__(256) void prep_weights(
    const float* __restrict__ W_wf, const float* __restrict__ W_ts,
    const float* __restrict__ W1)
{
    const int b = blockIdx.x;
    if (b < 128)       prep_tile(W_wf, WF_D, WF_D, WF_LEN, 1024, OFF_WF, b & 31, b >> 5);
    else if (b < 152)  { const int t = b - 128; prep_tile(W_ts, HID, HID, TS_FD, 96,  OFF_TS, t % 3,  t / 3); }
    else               { const int t = b - 152; prep_tile(W1,   FC_H, FC_H, 556,  576, OFF_W1, t % 18, t / 18); }
}

// ---------------------------------------------------------------------------
// Fused stage-2 reduce(4 partials) + bias + transpose + hi/lo split into the
// stage-4 B: Baug4[z][d][block*64 + {hi32|lo32}].  32x32 smem tiles.
// grid = (7 nwf-tiles, 4 d-tiles, 32 z).
// ---------------------------------------------------------------------------
__global__ __launch_bounds__(256) void reduce4_baug(const float* __restrict__ b_wf)
{
    __shared__ float s[32][33];          // [nwf][d]
    const int tid = threadIdx.x;
    const int w0 = blockIdx.x * 32;      // nwf tile
    const int d0 = blockIdx.y * 32;      // d tile
    const int z  = blockIdx.z;

    const int j  = tid & 31;
    const int i0 = (tid >> 5) * 4;
    const int d  = d0 + j;
    const float bias = (d < WF_D) ? b_wf[d] : 0.f;
#pragma unroll
    for (int r = 0; r < 4; r++) {
        const int nwf = w0 + i0 + r;
        float v = 0.f;
        if (nwf < N_WF && d < WF_D) {
            const long o = ((long)z * N_WF + nwf) * WF_D + d;
            v = g_P[o] + g_P[o + C1_ELEMS] + g_P[o + 2 * C1_ELEMS]
              + g_P[o + 3 * C1_ELEMS] + bias;
        }
        s[i0 + r][j] = v;
    }
    __syncthreads();

    const int dn = tid >> 3;
    const int wq = (tid & 7) * 4;
    __nv_bfloat16 hv[4], lv[4];
#pragma unroll
    for (int q = 0; q < 4; q++) {
        const float v = s[wq + q][dn];
        hv[q] = __float2bfloat16_rn(v);
        lv[q] = __float2bfloat16_rn(v - __bfloat162float(hv[q]));
    }
    __nv_bfloat16* row = g_Baug + OFF_B4 + (long)z * (128 * 448)
                       + (long)(d0 + dn) * 448 + blockIdx.x * 64 + wq;
    *(uint2*)(row)      = *(const uint2*)hv;   // hi
    *(uint2*)(row + 32) = *(const uint2*)lv;   // lo
}

// ---------------------------------------------------------------------------
// bf16 HMMA GEMM, hi/lo-interleaved precision split.
// Per 32-fp32-col block iteration: A loaded once (fp32 -> hi & lo bf16 smem),
// B block [hi32|lo32] loaded once; computes Ah*Bh + Al*Bh + Ah*Bl with Ah/Bh
// fragments reused from registers.  192 MMAs per warp between syncs.
// smem rows: 64 bf16 + 8 pad = 144 B (conflict-free ldmatrix, 4-bank shift).
// CTA 256 thr (8 warps), tile 128 x NT, warp tile WM x WN; double buffered.
// GATHER: A cols from texts / g_TS / g_SP (bounds 200/456, all /4).
// EPI_HEAD: fused relu + (256 -> 2) head GEMM + b2 -> outp.
// ---------------------------------------------------------------------------
template<int NT, int WM, int WN, int EPI, bool GATHER>
__global__ __launch_bounds__(256, 1) void hgemm(
    const float* __restrict__ A, int lda, long aStr,
    const float* __restrict__ A2, const float* __restrict__ A3,
    const __nv_bfloat16* __restrict__ Baug, long bStr, int KP3,
    float* __restrict__ C, int ldc, long cStr,
    int N, int K, int NC, int zChunkOff,
    const float* __restrict__ bias, float scale,
    const float* __restrict__ W2, const float* __restrict__ b2,
    float* __restrict__ outp)
{
    extern __shared__ char smem[];
    constexpr int MI   = WM / 16;
    constexpr int NI   = WN / 8;
    constexpr int NWC  = NT / WN;
    constexpr int ABUF = 128 * 144;            // bytes per A buffer
    constexpr int BBUF = NT * 144;

    const int tid  = threadIdx.x;
    const int lane = tid & 31;
    const int wid  = tid >> 5;
    const int wr   = wid / NWC;
    const int wc   = wid % NWC;

    A    += (long)blockIdx.z * aStr;
    Baug += (long)blockIdx.z * bStr;
    C    += (long)blockIdx.z * cStr;
    const int row0g = blockIdx.y * 128;

    const uint32_t sb = smem_u32(smem);
    const uint32_t aAddr = sb +
        (wr * WM + (lane & 15)) * 144 + (lane >> 4) * 16;
    const uint32_t bAddr = sb + 2 * ABUF +
        (wc * WN + (lane & 7) + (lane >> 4) * 8) * 144 + ((lane >> 3) & 1) * 16;

    float acc[MI][NI][4];
#pragma unroll
    for (int mi = 0; mi < MI; mi++)
#pragma unroll
        for (int ni = 0; ni < NI; ni++)
#pragma unroll
            for (int q = 0; q < 4; q++) acc[mi][ni][q] = 0.f;

    const int  arow = tid >> 1;          // A tile row
    const int  ch   = (tid & 1) * 16;    // fp32 col half within block
    const long rA   = row0g + arow;

    float4 va[4];
    uint4  vb[8];

    auto loadA = [&](int g) {
        const int s0 = g * 32 + ch;
#pragma unroll
        for (int q = 0; q < 4; q++) {
            const int sc = s0 + q * 4;
            float4 f = make_float4(0.f, 0.f, 0.f, 0.f);
            if (sc < K) {
                const float* p;
                if (!GATHER)                    p = A  + rA * (long)lda    + sc;
                else if (sc < TEXT_D)           p = A  + rA * (long)TEXT_D + sc;
                else if (sc < TEXT_D + HID)     p = A2 + rA * (long)HID    + (sc - TEXT_D);
                else                            p = A3 + rA * (long)WF_D   + (sc - TEXT_D - HID);
                f = *(const float4*)p;
            }
            va[q] = f;
        }
    };
    auto storeA = [&](int buf) {
        __nv_bfloat16 hv[16], lv[16];
        const float* vf = (const float*)va;
#pragma unroll
        for (int i = 0; i < 16; i++) {
            const float v = vf[i];
            hv[i] = __float2bfloat16_rn(v);
            lv[i] = __float2bfloat16_rn(v - __bfloat162float(hv[i]));
        }
        char* dst = smem + buf * ABUF + arow * 144 + ch * 2;
        *(uint4*)dst        = *(const uint4*)&hv[0];
        *(uint4*)(dst + 16) = *(const uint4*)&hv[8];
        *(uint4*)(dst + 64) = *(const uint4*)&lv[0];
        *(uint4*)(dst + 80) = *(const uint4*)&lv[8];
    };
    auto loadB = [&](int g) {
        if (tid < NT) {
            const uint4* p = (const uint4*)(Baug + (long)tid * (2 * KP3) + g * 64);
#pragma unroll
            for (int q = 0; q < 8; q++) vb[q] = p[q];
        }
    };
    auto storeB = [&](int buf) {
        if (tid < NT) {
            char* dst = smem + 2 * ABUF + buf * BBUF + tid * 144;
#pragma unroll
            for (int q = 0; q < 8; q++) *(uint4*)(dst + q * 16) = vb[q];
        }
    };

    const int g0 = blockIdx.z * zChunkOff;

    loadA(g0); loadB(g0);
    storeA(0); storeB(0);
    __syncthreads();

    for (int b = 0; b < NC; b++) {
        const int  p    = b & 1;
        const bool more = (b + 1 < NC);
        if (more) { loadA(g0 + b + 1); loadB(g0 + b + 1); }

        const uint32_t aP = aAddr + p * ABUF;
        const uint32_t bP = bAddr + p * BBUF;
#pragma unroll
        for (int kk = 0; kk < 2; kk++) {
            uint32_t ah[MI][4], bh[NI][2];
#pragma unroll
            for (int mi = 0; mi < MI; mi++)
                LDSM4(ah[mi][0], ah[mi][1], ah[mi][2], ah[mi][3],
                      aP + mi * (16 * 144) + kk * 32);
#pragma unroll
            for (int nb = 0; nb < NI / 2; nb++)
                LDSM4(bh[2 * nb][0], bh[2 * nb][1], bh[2 * nb + 1][0], bh[2 * nb + 1][1],
                      bP + nb * (16 * 144) + kk * 32);
#pragma unroll
            for (int mi = 0; mi < MI; mi++)
#pragma unroll
                for (int ni = 0; ni < NI; ni++)
                    MMA_BF16(acc[mi][ni], ah[mi], bh[ni]);      // Ah*Bh

            uint32_t al[MI][4];
#pragma unroll
            for (int mi = 0; mi < MI; mi++)
                LDSM4(al[mi][0], al[mi][1], al[mi][2], al[mi][3],
                      aP + mi * (16 * 144) + kk * 32 + 64);
#pragma unroll
            for (int mi = 0; mi < MI; mi++)
#pragma unroll
                for (int ni = 0; ni < NI; ni++)
                    MMA_BF16(acc[mi][ni], al[mi], bh[ni]);      // Al*Bh

            uint32_t bl[NI][2];
#pragma unroll
            for (int nb = 0; nb < NI / 2; nb++)
                LDSM4(bl[2 * nb][0], bl[2 * nb][1], bl[2 * nb + 1][0], bl[2 * nb + 1][1],
                      bP + nb * (16 * 144) + kk * 32 + 64);
#pragma unroll
            for (int mi = 0; mi < MI; mi++)
#pragma unroll
                for (int ni = 0; ni < NI; ni++)
                    MMA_BF16(acc[mi][ni], ah[mi], bl[ni]);      // Ah*Bl
        }

        if (more) { storeA(p ^ 1); storeB(p ^ 1); }
        __syncthreads();
    }

    // ---- epilogue: fragment (r = l/4 [+8], c = (l%4)*2) ----
    const int rw = row0g + wr * WM + (lane >> 2);
    const int cw = wc * WN + (lane & 3) * 2;

    if (EPI == EPI_HEAD) {
        float s[MI][2][2];
#pragma unroll
        for (int mi = 0; mi < MI; mi++)
#pragma unroll
            for (int pr = 0; pr < 2; pr++) { s[mi][pr][0] = 0.f; s[mi][pr][1] = 0.f; }
#pragma unroll
        for (int mi = 0; mi < MI; mi++) {
#pragma unroll
            for (int ni = 0; ni < NI; ni++) {
                const int col = cw + ni * 8;
                const float b0 = bias[col], b1v = bias[col + 1];
                const float w00 = W2[col * 2 + 0], w01 = W2[col * 2 + 1];
                const float w10 = W2[col * 2 + 2], w11 = W2[col * 2 + 3];
                float v0 = acc[mi][ni][0] + b0;  v0 = v0 > 0.f ? v0 : 0.f;
                float v1 = acc[mi][ni][1] + b1v; v1 = v1 > 0.f ? v1 : 0.f;
                float v2 = acc[mi][ni][2] + b0;  v2 = v2 > 0.f ? v2 : 0.f;
                float v3 = acc[mi][ni][3] + b1v; v3 = v3 > 0.f ? v3 : 0.f;
                s[mi][0][0] = fmaf(v0, w00, fmaf(v1, w10, s[mi][0][0]));
                s[mi][0][1] = fmaf(v0, w01, fmaf(v1, w11, s[mi][0][1]));
                s[mi][1][0] = fmaf(v2, w00, fmaf(v3, w10, s[mi][1][0]));
                s[mi][1][1] = fmaf(v2, w01, fmaf(v3, w11, s[mi][1][1]));
            }
        }
#pragma unroll
        for (int mi = 0; mi < MI; mi++)
#pragma unroll
            for (int pr = 0; pr < 2; pr++)
#pragma unroll
                for (int cl = 0; cl < 2; cl++) {
                    float v = s[mi][pr][cl];
                    v += __shfl_xor_sync(0xFFFFFFFFu, v, 1);
                    v += __shfl_xor_sync(0xFFFFFFFFu, v, 2);
                    s[mi][pr][cl] = v;
                }
        float* red = (float*)smem;
        __syncthreads();
        if ((lane & 3) == 0) {
            const int rbase = wr * WM + (lane >> 2);
#pragma unroll
            for (int mi = 0; mi < MI; mi++)
#pragma unroll
                for (int pr = 0; pr < 2; pr++) {
                    const int row = rbase + mi * 16 + pr * 8;
                    red[(wc * 128 + row) * 2 + 0] = s[mi][pr][0];
                    red[(wc * 128 + row) * 2 + 1] = s[mi][pr][1];
                }
        }
        __syncthreads();
        {
            const int row = tid >> 1;
            const int cl  = tid & 1;
            float v = red[(0 * 128 + row) * 2 + cl] + red[(1 * 128 + row) * 2 + cl]
                    + red[(2 * 128 + row) * 2 + cl] + red[(3 * 128 + row) * 2 + cl]
                    + b2[cl];
            outp[(long)(row0g + row) * 2 + cl] = v;
        }
        return;
    }

#pragma unroll
    for (int mi = 0; mi < MI; mi++) {
#pragma unroll
        for (int ni = 0; ni < NI; ni++) {
            const int col = cw + ni * 8;
            if (col < N) {
                float v0 = acc[mi][ni][0], v1 = acc[mi][ni][1];
                float v2 = acc[mi][ni][2], v3 = acc[mi][ni][3];
                if (EPI == EPI_TANH) {
                    const float b0 = bias[col], b1v = bias[col + 1];
                    v0 = tanhf(v0 + b0); v1 = tanhf(v1 + b1v);
                    v2 = tanhf(v2 + b0); v3 = tanhf(v3 + b1v);
                } else {  // SCALE
                    v0 *= scale; v1 *= scale; v2 *= scale; v3 *= scale;
                }
                const int r1 = rw + mi * 16;
                *(float2*)(C + (long)r1 * ldc + col)       = make_float2(v0, v1);
                *(float2*)(C + (long)(r1 + 8) * ldc + col) = make_float2(v2, v3);
            }
        }
    }
}

// ---------------------------------------------------------------------------
extern "C" void kernel_launch(void* const* d_in, const int* in_sizes, int n_in,
                              void* d_out, int out_size)
{
    const float* texts = (const float*)d_in[0];   // (512,32,200)
    const float* ts    = (const float*)d_in[1];   // (512,32,76)
    const float* wave  = (const float*)d_in[2];   // (32,200,1000)
    const float* wwm   = (const float*)d_in[3];   // (32,512,200)
    const float* W_wf  = (const float*)d_in[4];   // (1000,100)
    const float* b_wf  = (const float*)d_in[5];
    const float* W_ts  = (const float*)d_in[6];   // (76,256)
    const float* b_ts  = (const float*)d_in[7];
    const float* W1    = (const float*)d_in[8];   // (556,256)
    const float* b1    = (const float*)d_in[9];
    const float* W2    = (const float*)d_in[10];  // (256,2)
    const float* b2    = (const float*)d_in[11];
    float* out = (float*)d_out;

    float *P, *TS, *SP;
    __nv_bfloat16* Baug;
    cudaGetSymbolAddress((void**)&P,    g_P);
    cudaGetSymbolAddress((void**)&TS,   g_TS);
    cudaGetSymbolAddress((void**)&SP,   g_SP);
    cudaGetSymbolAddress((void**)&Baug, g_Baug);

    const int SMEM_N128 = 2 * 128 * 144 + 2 * 128 * 144;  // 73728
    const int SMEM_N256 = 2 * 128 * 144 + 2 * 256 * 144;  // 110592
    cudaFuncSetAttribute(hgemm<128, 32, 64, EPI_SCALE, false>,
                         cudaFuncAttributeMaxDynamicSharedMemorySize, SMEM_N128);
    cudaFuncSetAttribute(hgemm<256, 64, 64, EPI_TANH, false>,
                         cudaFuncAttributeMaxDynamicSharedMemorySize, SMEM_N256);
    cudaFuncSetAttribute(hgemm<256, 64, 64, EPI_HEAD, true>,
                         cudaFuncAttributeMaxDynamicSharedMemorySize, SMEM_N256);

    // 1) all weight preps, tiled transpose, one launch
    prep_weights<<<296, 256>>>(W_wf, W_ts, W1);

    // 2) stage 2: P[z] = partial(waveform @ W_wf), split-K=4
    //    (KP3=1024 -> 32 blocks, 8 per z). 200 CTAs.
    hgemm<128, 32, 64, EPI_SCALE, false><<<dim3(1, 50, 4), 256, SMEM_N128>>>(
        wave, WF_LEN, 0, nullptr, nullptr,
        Baug + OFF_WF, 0, 1024,
        P, WF_D, (long)C1_ELEMS,
        WF_D, WF_LEN, 8, 8, nullptr, 1.f, nullptr, nullptr, nullptr);

    // 3) stage 3: g_TS = tanh(ts @ W_ts + b_ts)  (KP3=96 -> 3 blocks)
    hgemm<256, 64, 64, EPI_TANH, false><<<dim3(1, 128, 1), 256, SMEM_N256>>>(
        ts, TS_FD, 0, nullptr, nullptr,
        Baug + OFF_TS, 0, 96,
        TS, HID, 0,
        HID, TS_FD, 3, 0, b_ts, 1.f, nullptr, nullptr, nullptr);

    // 4) fused reduce(4 partials)+bias -> stage-4 B (hi/lo interleaved)
    reduce4_baug<<<dim3(7, 4, 32), 256>>>(b_wf);

    // 5) stage 4: g_SP = bmm(wwm, wf_out) / 200  (KP3=224 -> 7 blocks; z=batch)
    hgemm<128, 32, 64, EPI_SCALE, false><<<dim3(1, 4, 32), 256, SMEM_N128>>>(
        wwm, N_WF, (long)T_DIM * N_WF, nullptr, nullptr,
        Baug + OFF_B4, (long)128 * 448, 224,
        SP, WF_D, (long)T_DIM * WF_D,
        WF_D, N_WF, 7, 0, nullptr, 1.f / (float)N_WF, nullptr, nullptr, nullptr);

    // 6) stage 5 + head fused:
    //    out = relu([texts|g_TS|g_SP] @ W1 + b1) @ W2 + b2  (KP3=576 -> 18 blocks)
    hgemm<256, 64, 64, EPI_HEAD, true><<<dim3(1, 128, 1), 256, SMEM_N256>>>(
        texts, 0, 0, TS, SP,
        Baug + OFF_W1, 0, 576,
        out, 0, 0,
        FC_H, 556, 18, 0, b1, 1.f, W2, b2, out);
}

// round 17
// speedup vs baseline: 2.8085x; 1.0912x over previous
#include <cuda_runtime.h>
#include <cuda_bf16.h>
#include <math.h>
#include <stdint.h>

// ---------------- shapes ----------------
#define T_DIM   512
#define B_DIM   32
#define TS_FD   76
#define N_WF    200
#define WF_LEN  1000
#define TEXT_D  200
#define WF_D    100
#define HID     256
#define FC_H    256
#define NCLS    2
#define ROWS    (T_DIM * B_DIM)          // 16384
#define C1_ELEMS (B_DIM * N_WF * WF_D)   // 640000

// g_Baug regions (elements). Layout per row: [2*KP3], each 32-block = [hi32|lo32]
#define OFF_WF  0L                        // 128 * 2048 = 262144
#define OFF_TS  262144L                   // 256 * 192  = 49152
#define OFF_W1  311296L                   // 256 * 1152 = 294912
#define OFF_B4  606208L                   // 32*128*448 = 1835008 (total 2441216)

// ---------------- scratch (__device__ globals; no cudaMalloc) ----------------
__device__ float g_P[4 * C1_ELEMS];            // stage-2 split-K partials
__device__ float g_TS[ROWS * HID];             // tanh(ts proj) (16384,256)
__device__ float g_SP[ROWS * WF_D];            // spread (16384,100), rows b*512+t
__device__ __align__(16) __nv_bfloat16 g_Baug[1 << 22];  // hi/lo-interleaved B

enum { EPI_TANH = 0, EPI_SCALE = 1, EPI_HEAD = 2 };

// ---------------- PTX helpers ----------------
__device__ __forceinline__ uint32_t smem_u32(const void* p) {
    uint32_t a;
    asm("{ .reg .u64 t; cvta.to.shared.u64 t, %1; cvt.u32.u64 %0, t; }" : "=r"(a) : "l"(p));
    return a;
}

#define LDSM4(r0, r1, r2, r3, a) \
    asm volatile("ldmatrix.sync.aligned.m8n8.x4.shared.b16 {%0,%1,%2,%3}, [%4];" \
        : "=r"(r0), "=r"(r1), "=r"(r2), "=r"(r3) : "r"(a))

#define MMA_BF16(d, a, b) \
    asm volatile("mma.sync.aligned.m16n8k16.row.col.f32.bf16.bf16.f32 " \
        "{%0,%1,%2,%3}, {%4,%5,%6,%7}, {%8,%9}, {%0,%1,%2,%3};" \
        : "+f"((d)[0]), "+f"((d)[1]), "+f"((d)[2]), "+f"((d)[3]) \
        : "r"((a)[0]), "r"((a)[1]), "r"((a)[2]), "r"((a)[3]), \
          "r"((b)[0]), "r"((b)[1]))

#define CP_ASYNC16(dst, src) \
    asm volatile("cp.async.cg.shared.global [%0], [%1], 16;" :: "r"(dst), "l"(src))
#define CP_COMMIT()  asm volatile("cp.async.commit_group;" ::: "memory")
#define CP_WAIT0()   asm volatile("cp.async.wait_group 0;" ::: "memory")

// ---------------------------------------------------------------------------
// Tiled weight prep: 32x32 smem transpose per block.
// src fp32 [K, N] (row stride ld); dst rows [NT][2*KP3]: block b at b*64,
// hi32 then lo32.  Zero padded (k >= K, n >= N).
// ---------------------------------------------------------------------------
__device__ __forceinline__ void prep_tile(
    const float* __restrict__ src, int ld, int N, int K, int KP3,
    long dstOff, int kt, int nt)
{
    __shared__ float s[32][33];
    const int tid = threadIdx.x;
    const int k0 = kt * 32, n0 = nt * 32;

    const int j  = tid & 31;
    const int i0 = (tid >> 5) * 4;
#pragma unroll
    for (int r = 0; r < 4; r++) {
        const int k = k0 + i0 + r;
        const int n = n0 + j;
        s[i0 + r][j] = (k < K && n < N) ? src[(long)k * ld + n] : 0.f;
    }
    __syncthreads();

    const int n  = tid >> 3;
    const int kq = (tid & 7) * 4;
    __nv_bfloat16 hv[4], lv[4];
#pragma unroll
    for (int q = 0; q < 4; q++) {
        const float v = s[kq + q][n];
        hv[q] = __float2bfloat16_rn(v);
        lv[q] = __float2bfloat16_rn(v - __bfloat162float(hv[q]));
    }
    __nv_bfloat16* row = g_Baug + dstOff + (long)(n0 + n) * (2 * KP3) + kt * 64 + kq;
    *(uint2*)(row)      = *(const uint2*)hv;   // hi
    *(uint2*)(row + 32) = *(const uint2*)lv;   // lo
}

// W_wf: 32 k-tiles x 4 n-tiles = 128 | W_ts: 3 x 8 = 24 | W1: 18 x 8 = 144
__global__ __launch_bounds__(256) void prep_weights(
    const float* __restrict__ W_wf, const float* __restrict__ W_ts,
    const float* __restrict__ W1)
{
    const int b = blockIdx.x;
    if (b < 128)       prep_tile(W_wf, WF_D, WF_D, WF_LEN, 1024, OFF_WF, b & 31, b >> 5);
    else if (b < 152)  { const int t = b - 128; prep_tile(W_ts, HID, HID, TS_FD, 96,  OFF_TS, t % 3,  t / 3); }
    else               { const int t = b - 152; prep_tile(W1,   FC_H, FC_H, 556,  576, OFF_W1, t % 18, t / 18); }
}

// ---------------------------------------------------------------------------
// Fused stage-2 reduce(4 partials) + bias + transpose + hi/lo split into the
// stage-4 B: Baug4[z][d][block*64 + {hi32|lo32}].  32x32 smem tiles.
// grid = (7 nwf-tiles, 4 d-tiles, 32 z).
// ---------------------------------------------------------------------------
__global__ __launch_bounds__(256) void reduce4_baug(const float* __restrict__ b_wf)
{
    __shared__ float s[32][33];          // [nwf][d]
    const int tid = threadIdx.x;
    const int w0 = blockIdx.x * 32;      // nwf tile
    const int d0 = blockIdx.y * 32;      // d tile
    const int z  = blockIdx.z;

    const int j  = tid & 31;
    const int i0 = (tid >> 5) * 4;
    const int d  = d0 + j;
    const float bias = (d < WF_D) ? b_wf[d] : 0.f;
#pragma unroll
    for (int r = 0; r < 4; r++) {
        const int nwf = w0 + i0 + r;
        float v = 0.f;
        if (nwf < N_WF && d < WF_D) {
            const long o = ((long)z * N_WF + nwf) * WF_D + d;
            v = g_P[o] + g_P[o + C1_ELEMS] + g_P[o + 2 * C1_ELEMS]
              + g_P[o + 3 * C1_ELEMS] + bias;
        }
        s[i0 + r][j] = v;
    }
    __syncthreads();

    const int dn = tid >> 3;
    const int wq = (tid & 7) * 4;
    __nv_bfloat16 hv[4], lv[4];
#pragma unroll
    for (int q = 0; q < 4; q++) {
        const float v = s[wq + q][dn];
        hv[q] = __float2bfloat16_rn(v);
        lv[q] = __float2bfloat16_rn(v - __bfloat162float(hv[q]));
    }
    __nv_bfloat16* row = g_Baug + OFF_B4 + (long)z * (128 * 448)
                       + (long)(d0 + dn) * 448 + blockIdx.x * 64 + wq;
    *(uint2*)(row)      = *(const uint2*)hv;   // hi
    *(uint2*)(row + 32) = *(const uint2*)lv;   // lo
}

// ---------------------------------------------------------------------------
// bf16 HMMA GEMM, hi/lo-interleaved precision split.  512 threads (16 warps),
// CTA tile 128 x NT, warp tile 32 x WN (warp grid 4 x 4).
// A: fp32 global -> regs -> hi/lo bf16 smem (conversion in-kernel).
// B: global bf16 -> smem via cp.async (no register staging).
// Per 32-col block: Ah*Bh + Al*Bh + Ah*Bl with Ah/Bh fragments reused.
// smem rows 144 B (64 bf16 + pad) -> conflict-free ldmatrix.
// GATHER: A cols from texts / g_TS / g_SP (bounds 200/456, all /4).
// EPI_HEAD: fused relu + (256 -> 2) head GEMM + b2 -> outp.
// ---------------------------------------------------------------------------
template<int NT, int WN, int EPI, bool GATHER>
__global__ __launch_bounds__(512, 1) void hgemm(
    const float* __restrict__ A, int lda, long aStr,
    const float* __restrict__ A2, const float* __restrict__ A3,
    const __nv_bfloat16* __restrict__ Baug, long bStr, int KP3,
    float* __restrict__ C, int ldc, long cStr,
    int N, int K, int NC, int zChunkOff,
    const float* __restrict__ bias, float scale,
    const float* __restrict__ W2, const float* __restrict__ b2,
    float* __restrict__ outp)
{
    extern __shared__ char smem[];
    constexpr int MI   = 2;                    // WM = 32
    constexpr int NI   = WN / 8;
    constexpr int ABUF = 128 * 144;            // bytes per A buffer
    constexpr int BBUF = NT * 144;

    const int tid  = threadIdx.x;
    const int lane = tid & 31;
    const int wid  = tid >> 5;
    const int wr   = wid >> 2;                 // 0..3 (row group of 32)
    const int wc   = wid & 3;                  // 0..3 (col group of WN)

    A    += (long)blockIdx.z * aStr;
    Baug += (long)blockIdx.z * bStr;
    C    += (long)blockIdx.z * cStr;
    const int row0g = blockIdx.y * 128;

    const uint32_t sb = smem_u32(smem);
    const uint32_t aAddr = sb +
        (wr * 32 + (lane & 15)) * 144 + (lane >> 4) * 16;
    const uint32_t bAddr = sb + 2 * ABUF +
        (wc * WN + (lane & 7) + (lane >> 4) * 8) * 144 + ((lane >> 3) & 1) * 16;

    float acc[MI][NI][4];
#pragma unroll
    for (int mi = 0; mi < MI; mi++)
#pragma unroll
        for (int ni = 0; ni < NI; ni++)
#pragma unroll
            for (int q = 0; q < 4; q++) acc[mi][ni][q] = 0.f;

    const int  arow = tid >> 2;          // A tile row (0..127)
    const int  ch   = (tid & 3) * 8;     // fp32 col offset within block (0..24)
    const long rA   = row0g + arow;

    float4 va[2];

    auto loadA = [&](int g) {
        const int s0 = g * 32 + ch;
#pragma unroll
        for (int q = 0; q < 2; q++) {
            const int sc = s0 + q * 4;
            float4 f = make_float4(0.f, 0.f, 0.f, 0.f);
            if (sc < K) {
                const float* p;
                if (!GATHER)                    p = A  + rA * (long)lda    + sc;
                else if (sc < TEXT_D)           p = A  + rA * (long)TEXT_D + sc;
                else if (sc < TEXT_D + HID)     p = A2 + rA * (long)HID    + (sc - TEXT_D);
                else                            p = A3 + rA * (long)WF_D   + (sc - TEXT_D - HID);
                f = *(const float4*)p;
            }
            va[q] = f;
        }
    };
    auto storeA = [&](int buf) {
        __nv_bfloat16 hv[8], lv[8];
        const float* vf = (const float*)va;
#pragma unroll
        for (int i = 0; i < 8; i++) {
            const float v = vf[i];
            hv[i] = __float2bfloat16_rn(v);
            lv[i] = __float2bfloat16_rn(v - __bfloat162float(hv[i]));
        }
        char* dst = smem + buf * ABUF + arow * 144 + ch * 2;
        *(uint4*)dst        = *(const uint4*)hv;
        *(uint4*)(dst + 64) = *(const uint4*)lv;
    };
    // B: cp.async straight into smem (NT*128 bytes per block tile)
    auto asyncB = [&](int g, int buf) {
        if (NT == 256) {
            const int row  = tid >> 1;
            const int half = tid & 1;
            const char* src = (const char*)(Baug + (long)row * (2 * KP3) + g * 64) + half * 64;
            const uint32_t dst = sb + 2 * ABUF + buf * BBUF + row * 144 + half * 64;
            CP_ASYNC16(dst,      src);
            CP_ASYNC16(dst + 16, src + 16);
            CP_ASYNC16(dst + 32, src + 32);
            CP_ASYNC16(dst + 48, src + 48);
        } else {
            const int row = tid >> 2;
            const int seg = tid & 3;
            const char* src = (const char*)(Baug + (long)row * (2 * KP3) + g * 64) + seg * 32;
            const uint32_t dst = sb + 2 * ABUF + buf * BBUF + row * 144 + seg * 32;
            CP_ASYNC16(dst,      src);
            CP_ASYNC16(dst + 16, src + 16);
        }
        CP_COMMIT();
    };

    const int g0 = blockIdx.z * zChunkOff;

    asyncB(g0, 0);
    loadA(g0);
    storeA(0);
    CP_WAIT0();
    __syncthreads();

    for (int b = 0; b < NC; b++) {
        const int  p    = b & 1;
        const bool more = (b + 1 < NC);
        if (more) { asyncB(g0 + b + 1, p ^ 1); loadA(g0 + b + 1); }

        const uint32_t aP = aAddr + p * ABUF;
        const uint32_t bP = bAddr + p * BBUF;
#pragma unroll
        for (int kk = 0; kk < 2; kk++) {
            uint32_t ah[MI][4], bh[NI][2];
#pragma unroll
            for (int mi = 0; mi < MI; mi++)
                LDSM4(ah[mi][0], ah[mi][1], ah[mi][2], ah[mi][3],
                      aP + mi * (16 * 144) + kk * 32);
#pragma unroll
            for (int nb = 0; nb < NI / 2; nb++)
                LDSM4(bh[2 * nb][0], bh[2 * nb][1], bh[2 * nb + 1][0], bh[2 * nb + 1][1],
                      bP + nb * (16 * 144) + kk * 32);
#pragma unroll
            for (int mi = 0; mi < MI; mi++)
#pragma unroll
                for (int ni = 0; ni < NI; ni++)
                    MMA_BF16(acc[mi][ni], ah[mi], bh[ni]);      // Ah*Bh

            uint32_t al[MI][4];
#pragma unroll
            for (int mi = 0; mi < MI; mi++)
                LDSM4(al[mi][0], al[mi][1], al[mi][2], al[mi][3],
                      aP + mi * (16 * 144) + kk * 32 + 64);
#pragma unroll
            for (int mi = 0; mi < MI; mi++)
#pragma unroll
                for (int ni = 0; ni < NI; ni++)
                    MMA_BF16(acc[mi][ni], al[mi], bh[ni]);      // Al*Bh

            uint32_t bl[NI][2];
#pragma unroll
            for (int nb = 0; nb < NI / 2; nb++)
                LDSM4(bl[2 * nb][0], bl[2 * nb][1], bl[2 * nb + 1][0], bl[2 * nb + 1][1],
                      bP + nb * (16 * 144) + kk * 32 + 64);
#pragma unroll
            for (int mi = 0; mi < MI; mi++)
#pragma unroll
                for (int ni = 0; ni < NI; ni++)
                    MMA_BF16(acc[mi][ni], ah[mi], bl[ni]);      // Ah*Bl
        }

        if (more) storeA(p ^ 1);
        CP_WAIT0();
        __syncthreads();
    }

    // ---- epilogue: fragment (r = l/4 [+8], c = (l%4)*2) ----
    const int rw = row0g + wr * 32 + (lane >> 2);
    const int cw = wc * WN + (lane & 3) * 2;

    if (EPI == EPI_HEAD) {
        float s[MI][2][2];
#pragma unroll
        for (int mi = 0; mi < MI; mi++)
#pragma unroll
            for (int pr = 0; pr < 2; pr++) { s[mi][pr][0] = 0.f; s[mi][pr][1] = 0.f; }
#pragma unroll
        for (int mi = 0; mi < MI; mi++) {
#pragma unroll
            for (int ni = 0; ni < NI; ni++) {
                const int col = cw + ni * 8;
                const float b0 = bias[col], b1v = bias[col + 1];
                const float w00 = W2[col * 2 + 0], w01 = W2[col * 2 + 1];
                const float w10 = W2[col * 2 + 2], w11 = W2[col * 2 + 3];
                float v0 = acc[mi][ni][0] + b0;  v0 = v0 > 0.f ? v0 : 0.f;
                float v1 = acc[mi][ni][1] + b1v; v1 = v1 > 0.f ? v1 : 0.f;
                float v2 = acc[mi][ni][2] + b0;  v2 = v2 > 0.f ? v2 : 0.f;
                float v3 = acc[mi][ni][3] + b1v; v3 = v3 > 0.f ? v3 : 0.f;
                s[mi][0][0] = fmaf(v0, w00, fmaf(v1, w10, s[mi][0][0]));
                s[mi][0][1] = fmaf(v0, w01, fmaf(v1, w11, s[mi][0][1]));
                s[mi][1][0] = fmaf(v2, w00, fmaf(v3, w10, s[mi][1][0]));
                s[mi][1][1] = fmaf(v2, w01, fmaf(v3, w11, s[mi][1][1]));
            }
        }
#pragma unroll
        for (int mi = 0; mi < MI; mi++)
#pragma unroll
            for (int pr = 0; pr < 2; pr++)
#pragma unroll
                for (int cl = 0; cl < 2; cl++) {
                    float v = s[mi][pr][cl];
                    v += __shfl_xor_sync(0xFFFFFFFFu, v, 1);
                    v += __shfl_xor_sync(0xFFFFFFFFu, v, 2);
                    s[mi][pr][cl] = v;
                }
        float* red = (float*)smem;
        __syncthreads();
        if ((lane & 3) == 0) {
            const int rbase = wr * 32 + (lane >> 2);
#pragma unroll
            for (int mi = 0; mi < MI; mi++)
#pragma unroll
                for (int pr = 0; pr < 2; pr++) {
                    const int row = rbase + mi * 16 + pr * 8;
                    red[(wc * 128 + row) * 2 + 0] = s[mi][pr][0];
                    red[(wc * 128 + row) * 2 + 1] = s[mi][pr][1];
                }
        }
        __syncthreads();
        if (tid < 256) {
            const int row = tid >> 1;
            const int cl  = tid & 1;
            float v = red[(0 * 128 + row) * 2 + cl] + red[(1 * 128 + row) * 2 + cl]
                    + red[(2 * 128 + row) * 2 + cl] + red[(3 * 128 + row) * 2 + cl]
                    + b2[cl];
            outp[(long)(row0g + row) * 2 + cl] = v;
        }
        return;
    }

#pragma unroll
    for (int mi = 0; mi < MI; mi++) {
#pragma unroll
        for (int ni = 0; ni < NI; ni++) {
            const int col = cw + ni * 8;
            if (col < N) {
                float v0 = acc[mi][ni][0], v1 = acc[mi][ni][1];
                float v2 = acc[mi][ni][2], v3 = acc[mi][ni][3];
                if (EPI == EPI_TANH) {
                    const float b0 = bias[col], b1v = bias[col + 1];
                    v0 = tanhf(v0 + b0); v1 = tanhf(v1 + b1v);
                    v2 = tanhf(v2 + b0); v3 = tanhf(v3 + b1v);
                } else {  // SCALE
                    v0 *= scale; v1 *= scale; v2 *= scale; v3 *= scale;
                }
                const int r1 = rw + mi * 16;
                *(float2*)(C + (long)r1 * ldc + col)       = make_float2(v0, v1);
                *(float2*)(C + (long)(r1 + 8) * ldc + col) = make_float2(v2, v3);
            }
        }
    }
}

// ---------------------------------------------------------------------------
extern "C" void kernel_launch(void* const* d_in, const int* in_sizes, int n_in,
                              void* d_out, int out_size)
{
    const float* texts = (const float*)d_in[0];   // (512,32,200)
    const float* ts    = (const float*)d_in[1];   // (512,32,76)
    const float* wave  = (const float*)d_in[2];   // (32,200,1000)
    const float* wwm   = (const float*)d_in[3];   // (32,512,200)
    const float* W_wf  = (const float*)d_in[4];   // (1000,100)
    const float* b_wf  = (const float*)d_in[5];
    const float* W_ts  = (const float*)d_in[6];   // (76,256)
    const float* b_ts  = (const float*)d_in[7];
    const float* W1    = (const float*)d_in[8];   // (556,256)
    const float* b1    = (const float*)d_in[9];
    const float* W2    = (const float*)d_in[10];  // (256,2)
    const float* b2    = (const float*)d_in[11];
    float* out = (float*)d_out;

    float *P, *TS, *SP;
    __nv_bfloat16* Baug;
    cudaGetSymbolAddress((void**)&P,    g_P);
    cudaGetSymbolAddress((void**)&TS,   g_TS);
    cudaGetSymbolAddress((void**)&SP,   g_SP);
    cudaGetSymbolAddress((void**)&Baug, g_Baug);

    const int SMEM_N128 = 2 * 128 * 144 + 2 * 128 * 144;  // 73728
    const int SMEM_N256 = 2 * 128 * 144 + 2 * 256 * 144;  // 110592
    cudaFuncSetAttribute(hgemm<128, 32, EPI_SCALE, false>,
                         cudaFuncAttributeMaxDynamicSharedMemorySize, SMEM_N128);
    cudaFuncSetAttribute(hgemm<256, 64, EPI_TANH, false>,
                         cudaFuncAttributeMaxDynamicSharedMemorySize, SMEM_N256);
    cudaFuncSetAttribute(hgemm<256, 64, EPI_HEAD, true>,
                         cudaFuncAttributeMaxDynamicSharedMemorySize, SMEM_N256);

    // 1) all weight preps, tiled transpose, one launch
    prep_weights<<<296, 256>>>(W_wf, W_ts, W1);

    // 2) stage 2: P[z] = partial(waveform @ W_wf), split-K=4
    //    (KP3=1024 -> 32 blocks, 8 per z). 200 CTAs.
    hgemm<128, 32, EPI_SCALE, false><<<dim3(1, 50, 4), 512, SMEM_N128>>>(
        wave, WF_LEN, 0, nullptr, nullptr,
        Baug + OFF_WF, 0, 1024,
        P, WF_D, (long)C1_ELEMS,
        WF_D, WF_LEN, 8, 8, nullptr, 1.f, nullptr, nullptr, nullptr);

    // 3) stage 3: g_TS = tanh(ts @ W_ts + b_ts)  (KP3=96 -> 3 blocks)
    hgemm<256, 64, EPI_TANH, false><<<dim3(1, 128, 1), 512, SMEM_N256>>>(
        ts, TS_FD, 0, nullptr, nullptr,
        Baug + OFF_TS, 0, 96,
        TS, HID, 0,
        HID, TS_FD, 3, 0, b_ts, 1.f, nullptr, nullptr, nullptr);

    // 4) fused reduce(4 partials)+bias -> stage-4 B (hi/lo interleaved)
    reduce4_baug<<<dim3(7, 4, 32), 256>>>(b_wf);

    // 5) stage 4: g_SP = bmm(wwm, wf_out) / 200  (KP3=224 -> 7 blocks; z=batch)
    hgemm<128, 32, EPI_SCALE, false><<<dim3(1, 4, 32), 512, SMEM_N128>>>(
        wwm, N_WF, (long)T_DIM * N_WF, nullptr, nullptr,
        Baug + OFF_B4, (long)128 * 448, 224,
        SP, WF_D, (long)T_DIM * WF_D,
        WF_D, N_WF, 7, 0, nullptr, 1.f / (float)N_WF, nullptr, nullptr, nullptr);

    // 6) stage 5 + head fused:
    //    out = relu([texts|g_TS|g_SP] @ W1 + b1) @ W2 + b2  (KP3=576 -> 18 blocks)
    hgemm<256, 64, EPI_HEAD, true><<<dim3(1, 128, 1), 512, SMEM_N256>>>(
        texts, 0, 0, TS, SP,
        Baug + OFF_W1, 0, 576,
        out, 0, 0,
        FC_H, 556, 18, 0, b1, 1.f, W2, b2, out);
}